// round 1
// baseline (speedup 1.0000x reference)
#include <cuda_runtime.h>
#include <cstdint>

#define HDIM 64
#define NODE_DIM 92
#define EDGE_DIM 41
#define KDIM 169          // 2H + EDGE_DIM
#define OUTC 128          // 2H
#define PRED_H 128
#define BN_EPS 1e-5f
#define MAX_NODES 100000
#define MAX_EDGES 1600000
#define MAX_GRAPHS 4096

#define TE 128            // edges per GEMM tile
#define XSTR 172          // padded x row stride (floats)
#define CONV_SMEM_FLOATS (KDIM*OUTC + TE*XSTR)

// ------------------------- scratch (static device allocs) -------------------
__device__ float g_h[MAX_NODES * HDIM];                  // node hidden state
__device__ float g_z[(size_t)MAX_EDGES * OUTC];          // pre-BN edge activations (819MB)
__device__ float g_sum[OUTC];                            // BN col sums (self-zeroing)
__device__ float g_sumsq[OUTC];
__device__ float g_coef[2 * OUTC];                       // BN scale/shift
__device__ float g_pool[MAX_GRAPHS * HDIM];              // graph pooling (self-zeroing)
__device__ float g_cnt[MAX_GRAPHS];

// ------------------------- helpers ------------------------------------------
__device__ __forceinline__ void ffma2(unsigned long long &d, unsigned long long a,
                                      unsigned long long b) {
    asm("fma.rn.f32x2 %0, %1, %2, %0;" : "+l"(d) : "l"(a), "l"(b));
}
__device__ __forceinline__ unsigned long long bcast2(float x) {
    unsigned long long r;
    asm("mov.b64 %0, {%1, %1};" : "=l"(r) : "f"(x));
    return r;
}
__device__ __forceinline__ float f2lo(unsigned long long v) { return __uint_as_float((unsigned)v); }
__device__ __forceinline__ float f2hi(unsigned long long v) { return __uint_as_float((unsigned)(v >> 32)); }

__device__ __forceinline__ float softplusf(float x) {
    return fmaxf(x, 0.f) + log1pf(expf(-fabsf(x)));
}
__device__ __forceinline__ float sigmoidf(float x) {
    return 1.f / (1.f + expf(-x));
}

// ------------------------- 1. node embedding --------------------------------
__global__ void __launch_bounds__(256)
emb_kernel(const float* __restrict__ nf, const float* __restrict__ Wm,
           const float* __restrict__ b, int nNodes) {
    __shared__ float sW[NODE_DIM * HDIM];
    __shared__ float sXn[8][NODE_DIM];
    for (int i = threadIdx.x; i < NODE_DIM * HDIM; i += 256) sW[i] = Wm[i];
    __syncthreads();
    int wid = threadIdx.x >> 5, lane = threadIdx.x & 31;
    int gw = (blockIdx.x * 256 + threadIdx.x) >> 5;
    int nW = (gridDim.x * 256) >> 5;
    float b0 = b[lane], b1 = b[lane + 32];
    for (int n = gw; n < nNodes; n += nW) {
        __syncwarp();
        for (int k = lane; k < NODE_DIM; k += 32) sXn[wid][k] = nf[(size_t)n * NODE_DIM + k];
        __syncwarp();
        float a0 = b0, a1 = b1;
        #pragma unroll 4
        for (int k = 0; k < NODE_DIM; k++) {
            float xv = sXn[wid][k];
            a0 = fmaf(xv, sW[k * HDIM + lane], a0);
            a1 = fmaf(xv, sW[k * HDIM + lane + 32], a1);
        }
        g_h[(size_t)n * HDIM + lane] = a0;
        g_h[(size_t)n * HDIM + lane + 32] = a1;
    }
}

// ------------------------- 2. conv edge GEMM + BN stats ---------------------
// z[e] = concat(h[src], h[dst], ef[e]) @ W   (bias omitted: it cancels in BN,
// and conv_b is zeros). Each thread: 8 edges x 8 cols via f32x2 FMA.
// Thread cols: {tx*4 .. tx*4+3} and {64+tx*4 .. 64+tx*4+3} (conflict-free LDS.128).
__global__ void __launch_bounds__(256, 1)
conv_gemm_kernel(const float* __restrict__ W, const float* __restrict__ ef,
                 const int* __restrict__ ei, int nEdges, int nTiles) {
    extern __shared__ __align__(16) float smem[];
    float* sW = smem;                     // KDIM*OUTC
    float* sX = smem + KDIM * OUTC;       // TE*XSTR
    const int tid  = threadIdx.x;
    const int tx   = tid & 15;
    const int ty   = tid >> 4;
    const int wid  = tid >> 5;
    const int lane = tid & 31;

    for (int i = tid; i < KDIM * OUTC; i += 256) sW[i] = W[i];

    float csum[8], csumsq[8];
    #pragma unroll
    for (int j = 0; j < 8; j++) { csum[j] = 0.f; csumsq[j] = 0.f; }

    for (int t = blockIdx.x; t < nTiles; t += gridDim.x) {
        __syncthreads();   // protect sX from previous tile's readers
        const int e0 = t * TE;

        // gather: 8 warps, 16 rows each
        for (int r = wid; r < TE; r += 8) {
            int e = e0 + r;
            float* xr = sX + r * XSTR;
            if (e < nEdges) {
                int s = ei[e];
                int d = ei[nEdges + e];
                if (lane < 16)
                    ((float4*)xr)[lane] = ((const float4*)(g_h + (size_t)s * HDIM))[lane];
                else
                    ((float4*)(xr + HDIM))[lane - 16] =
                        ((const float4*)(g_h + (size_t)d * HDIM))[lane - 16];
                const float* efr = ef + (size_t)e * EDGE_DIM;
                xr[2 * HDIM + lane] = efr[lane];
                if (lane < EDGE_DIM - 32) xr[2 * HDIM + 32 + lane] = efr[32 + lane];
            } else {
                float4 z4 = make_float4(0.f, 0.f, 0.f, 0.f);
                if (lane < 16) ((float4*)xr)[lane] = z4;
                else           ((float4*)(xr + HDIM))[lane - 16] = z4;
                xr[2 * HDIM + lane] = 0.f;
                if (lane < EDGE_DIM - 32) xr[2 * HDIM + 32 + lane] = 0.f;
            }
        }
        __syncthreads();

        unsigned long long acc[8][4];
        #pragma unroll
        for (int i = 0; i < 8; i++)
            #pragma unroll
            for (int p = 0; p < 4; p++) acc[i][p] = 0ULL;

        const float* xbase = sX + ty * XSTR;
        const float* wbase = sW + tx * 4;
        for (int k = 0; k < KDIM; k++) {
            ulonglong2 wA = *(const ulonglong2*)(wbase + k * OUTC);
            ulonglong2 wB = *(const ulonglong2*)(wbase + k * OUTC + HDIM);
            #pragma unroll
            for (int i = 0; i < 8; i++) {
                unsigned long long xp = bcast2(xbase[k + i * 16 * XSTR]);
                ffma2(acc[i][0], xp, wA.x);
                ffma2(acc[i][1], xp, wA.y);
                ffma2(acc[i][2], xp, wB.x);
                ffma2(acc[i][3], xp, wB.y);
            }
        }

        #pragma unroll
        for (int i = 0; i < 8; i++) {
            int e = e0 + ty + 16 * i;
            if (e < nEdges) {
                float* zr = g_z + (size_t)e * OUTC;
                *(ulonglong2*)(zr + tx * 4)        = make_ulonglong2(acc[i][0], acc[i][1]);
                *(ulonglong2*)(zr + HDIM + tx * 4) = make_ulonglong2(acc[i][2], acc[i][3]);
                #pragma unroll
                for (int p = 0; p < 4; p++) {
                    float lo = f2lo(acc[i][p]), hi = f2hi(acc[i][p]);
                    csum[2 * p]     += lo;  csumsq[2 * p]     += lo * lo;
                    csum[2 * p + 1] += hi;  csumsq[2 * p + 1] += hi * hi;
                }
            }
        }
    }

    // block-level BN stats reduction (reuse sX)
    __syncthreads();
    float* red = sX;
    #pragma unroll
    for (int j = 0; j < 8; j++) {
        red[tid * 8 + j]        = csum[j];
        red[2048 + tid * 8 + j] = csumsq[j];
    }
    __syncthreads();
    if (tid < 16) {
        for (int j = 0; j < 8; j++) {
            float s = 0.f, ss = 0.f;
            for (int yy = 0; yy < 16; yy++) {
                s  += red[(yy * 16 + tid) * 8 + j];
                ss += red[2048 + (yy * 16 + tid) * 8 + j];
            }
            int p = j >> 1;
            int col = (p < 2 ? tid * 4 + 2 * p : HDIM + tid * 4 + 2 * (p - 2)) + (j & 1);
            atomicAdd(&g_sum[col], s);
            atomicAdd(&g_sumsq[col], ss);
        }
    }
}

// ------------------------- 3. BN coefficients (self-zeroing stats) ----------
__global__ void bn_coef_kernel(const float* __restrict__ gamma,
                               const float* __restrict__ beta, float invE) {
    int c = threadIdx.x;
    float s = g_sum[c], ss = g_sumsq[c];
    float mean = s * invE;
    float var  = fmaf(-mean, mean, ss * invE);
    float a    = gamma[c] * rsqrtf(var + BN_EPS);
    g_coef[c]        = a;
    g_coef[OUTC + c] = fmaf(-mean, a, beta[c]);
    g_sum[c] = 0.f;
    g_sumsq[c] = 0.f;
}

// ------------------------- 4. gate + scatter-add ----------------------------
__global__ void __launch_bounds__(256)
gate_scatter_kernel(const int* __restrict__ ei, int nEdges) {
    __shared__ float sc[2 * OUTC];
    sc[threadIdx.x] = g_coef[threadIdx.x];   // blockDim == 256 == 2*OUTC
    __syncthreads();
    int gid = blockIdx.x * 256 + threadIdx.x;
    int e = gid >> 5;
    if (e >= nEdges) return;
    int lane = gid & 31;
    int s = ei[e];
    const float* zr = g_z + (size_t)e * OUTC;
    float n0 = fmaf(zr[lane],      sc[lane],      sc[OUTC + lane]);
    float n1 = fmaf(zr[lane + 32], sc[lane + 32], sc[OUTC + lane + 32]);
    float n2 = fmaf(zr[lane + 64], sc[lane + 64], sc[OUTC + lane + 64]);
    float n3 = fmaf(zr[lane + 96], sc[lane + 96], sc[OUTC + lane + 96]);
    float m0 = sigmoidf(n0) * softplusf(n2);
    float m1 = sigmoidf(n1) * softplusf(n3);
    float* hr = g_h + (size_t)s * HDIM;
    atomicAdd(hr + lane, m0);
    atomicAdd(hr + lane + 32, m1);
}

// ------------------------- 5. graph mean pooling ----------------------------
__global__ void __launch_bounds__(256)
pool_kernel(const int* __restrict__ gidArr, int nNodes) {
    int gid = blockIdx.x * 256 + threadIdx.x;
    int n = gid >> 5;
    if (n >= nNodes) return;
    int lane = gid & 31;
    int g = gidArr[n];
    atomicAdd(&g_pool[(size_t)g * HDIM + lane],      g_h[(size_t)n * HDIM + lane]);
    atomicAdd(&g_pool[(size_t)g * HDIM + lane + 32], g_h[(size_t)n * HDIM + lane + 32]);
    if (lane == 0) atomicAdd(&g_cnt[g], 1.0f);
}

// ------------------------- 6. prediction head (self-zeroing pool) -----------
__global__ void __launch_bounds__(PRED_H)
head_kernel(const float* __restrict__ fcW, const float* __restrict__ fcb,
            const float* __restrict__ outW, const float* __restrict__ outb,
            float* __restrict__ out) {
    __shared__ float sp[HDIM];
    __shared__ float red[PRED_H];
    int g = blockIdx.x, t = threadIdx.x;
    if (t < HDIM) {
        float c = g_cnt[g];
        sp[t] = g_pool[(size_t)g * HDIM + t] / fmaxf(c, 1.0f);
    }
    __syncthreads();
    float acc = fcb[t];
    #pragma unroll
    for (int k = 0; k < HDIM; k++) acc = fmaf(sp[k], fcW[k * PRED_H + t], acc);
    red[t] = softplusf(acc) * outW[t];
    __syncthreads();
    for (int sft = PRED_H / 2; sft > 0; sft >>= 1) {
        if (t < sft) red[t] += red[t + sft];
        __syncthreads();
    }
    if (t == 0) out[g] = red[0] + outb[0];
    __syncthreads();
    if (t < HDIM) g_pool[(size_t)g * HDIM + t] = 0.f;   // leave zeroed for next call
    if (t == HDIM) g_cnt[g] = 0.f;
}

// ------------------------- launch -------------------------------------------
extern "C" void kernel_launch(void* const* d_in, const int* in_sizes, int n_in,
                              void* d_out, int out_size) {
    const float* node_feats = (const float*)d_in[0];
    const int*   edge_index = (const int*)d_in[1];
    const float* edge_feats = (const float*)d_in[2];
    const int*   graph_id   = (const int*)d_in[3];
    const float* emb_W      = (const float*)d_in[4];
    const float* emb_b      = (const float*)d_in[5];
    const float* conv_W     = (const float*)d_in[6];
    // d_in[7] = conv_b: zeros, and any constant bias cancels exactly in BN.
    const float* bn_gamma   = (const float*)d_in[8];
    const float* bn_beta    = (const float*)d_in[9];
    const float* fc_W       = (const float*)d_in[10];
    const float* fc_b       = (const float*)d_in[11];
    const float* out_W      = (const float*)d_in[12];
    const float* out_b      = (const float*)d_in[13];

    int nNodes  = in_sizes[0] / NODE_DIM;
    int nEdges  = in_sizes[1] / 2;
    int nGraphs = out_size;
    int nConv   = in_sizes[6] / (KDIM * OUTC);

    int nsm = 148;
    cudaDeviceGetAttribute(&nsm, cudaDevAttrMultiProcessorCount, 0);

    size_t convSmem = (size_t)CONV_SMEM_FLOATS * sizeof(float);  // 174592 B
    cudaFuncSetAttribute(conv_gemm_kernel,
                         cudaFuncAttributeMaxDynamicSharedMemorySize, (int)convSmem);

    emb_kernel<<<2048, 256>>>(node_feats, emb_W, emb_b, nNodes);

    int nTiles = (nEdges + TE - 1) / TE;
    float invE = 1.0f / (float)nEdges;
    for (int l = 0; l < nConv; l++) {
        conv_gemm_kernel<<<nsm, 256, convSmem>>>(conv_W + (size_t)l * KDIM * OUTC,
                                                 edge_feats, edge_index, nEdges, nTiles);
        bn_coef_kernel<<<1, OUTC>>>(bn_gamma + l * OUTC, bn_beta + l * OUTC, invE);
        int gblocks = (int)(((long long)nEdges * 32 + 255) / 256);
        gate_scatter_kernel<<<gblocks, 256>>>(edge_index, nEdges);
    }

    pool_kernel<<<(int)(((long long)nNodes * 32 + 255) / 256), 256>>>(graph_id, nNodes);
    head_kernel<<<nGraphs, PRED_H>>>(fc_W, fc_b, out_W, out_b, (float*)d_out);
}

// round 3
// speedup vs baseline: 1.1389x; 1.1389x over previous
#include <cuda_runtime.h>
#include <cuda_bf16.h>
#include <cuda_fp16.h>
#include <cstdint>

#define HDIM 64
#define NODE_DIM 92
#define EDGE_DIM 41
#define KD 169            // 2H + EDGE_DIM
#define OUTC 128          // 2H
#define PRED_H 128
#define BN_EPS 1e-5f
#define MAX_NODES 100000
#define MAX_EDGES 1600000
#define MAX_GRAPHS 4096

#define NB 22             // B k16-chunks: [0,11)=hi, [11,22)=lo
#define NS 33             // MMA k-steps per tile
#define ASTRIDE 180       // A smem row stride (u32 words): 352 bf16 data + pad
#define AWORDS (128 * ASTRIDE)           // 23040 words
#define BU2    (NB * 16 * 32)            // 11264 uint2 = 90112 B
#define ZSTRIDE 68                       // z smem row stride (words)
#define ZWORDS (128 * ZSTRIDE)           // 8704 words
#define SMEM_WORDS (AWORDS + 2 * BU2 + ZWORDS)   // 54272 words = 217088 B

// ------------------------- device scratch ------------------------------------
__device__ float  g_h[MAX_NODES * HDIM];
__device__ __half g_zh[(size_t)MAX_EDGES * OUTC];   // fp16 pre-BN activations
__device__ float  g_sum[OUTC];
__device__ float  g_sumsq[OUTC];
__device__ float  g_coef[2 * OUTC];
__device__ float  g_pool[MAX_GRAPHS * HDIM];
__device__ float  g_cnt[MAX_GRAPHS];
__device__ __align__(16) uint2 g_bfrag[BU2];        // precomputed B fragments

// ------------------------- helpers ------------------------------------------
__device__ __forceinline__ float softplusf(float x) {
    return fmaxf(x, 0.f) + log1pf(expf(-fabsf(x)));
}
__device__ __forceinline__ float sigmoidf(float x) { return 1.f / (1.f + expf(-x)); }

// mma.sync m16n8k16 row.col f32 += bf16*bf16 (base PTX, sm_80+)
__device__ __forceinline__ void mma16816(float* d, const uint32_t* a, uint2 b) {
    asm volatile("mma.sync.aligned.m16n8k16.row.col.f32.bf16.bf16.f32 "
                 "{%0,%1,%2,%3}, {%4,%5,%6,%7}, {%8,%9}, {%0,%1,%2,%3};"
                 : "+f"(d[0]), "+f"(d[1]), "+f"(d[2]), "+f"(d[3])
                 : "r"(a[0]), "r"(a[1]), "r"(a[2]), "r"(a[3]), "r"(b.x), "r"(b.y));
}

// write hi pair at even col (c0,c0+1) and lo pair at word +88 (col +176)
__device__ __forceinline__ void put2(uint32_t* row, int c0, float f0, float f1) {
    uint32_t hip;
    asm("cvt.rn.satfinite.bf16x2.f32 %0, %1, %2;" : "=r"(hip) : "f"(f1), "f"(f0));
    float h0 = __uint_as_float(hip << 16);
    float h1 = __uint_as_float(hip & 0xffff0000u);
    uint32_t lop;
    asm("cvt.rn.satfinite.bf16x2.f32 %0, %1, %2;" : "=r"(lop) : "f"(f1 - h1), "f"(f0 - h0));
    int w = c0 >> 1;
    row[w]      = hip;
    row[w + 88] = lop;
}

// ------------------------- 1. node embedding --------------------------------
__global__ void __launch_bounds__(256)
emb_kernel(const float* __restrict__ nf, const float* __restrict__ Wm,
           const float* __restrict__ b, int nNodes) {
    __shared__ float sW[NODE_DIM * HDIM];
    __shared__ float sXn[8][NODE_DIM];
    for (int i = threadIdx.x; i < NODE_DIM * HDIM; i += 256) sW[i] = Wm[i];
    __syncthreads();
    int wid = threadIdx.x >> 5, lane = threadIdx.x & 31;
    int gw = (blockIdx.x * 256 + threadIdx.x) >> 5;
    int nW = (gridDim.x * 256) >> 5;
    float b0 = b[lane], b1 = b[lane + 32];
    for (int n = gw; n < nNodes; n += nW) {
        __syncwarp();
        for (int k = lane; k < NODE_DIM; k += 32) sXn[wid][k] = nf[(size_t)n * NODE_DIM + k];
        __syncwarp();
        float a0 = b0, a1 = b1;
        #pragma unroll 4
        for (int k = 0; k < NODE_DIM; k++) {
            float xv = sXn[wid][k];
            a0 = fmaf(xv, sW[k * HDIM + lane], a0);
            a1 = fmaf(xv, sW[k * HDIM + lane + 32], a1);
        }
        g_h[(size_t)n * HDIM + lane] = a0;
        g_h[(size_t)n * HDIM + lane + 32] = a1;
    }
}

// ------------------------- 2a. B fragment precompute -------------------------
// b-frag for mma m16n8k16 col-major: lane t holds B[k0+{0,1}][n] and
// B[k0+8+{0,1}][n], k0 = 2*(t%4), n = t/4.  chunks 0..10 = W_hi, 11..21 = W_lo.
__global__ void __launch_bounds__(256)
bfrag_kernel(const float* __restrict__ W) {
    int idx = blockIdx.x * 256 + threadIdx.x;
    if (idx >= BU2) return;
    int lane = idx & 31;
    int nt   = (idx >> 5) & 15;
    int bi   = idx >> 9;              // 0..21
    int seg  = bi >= 11;
    int c    = bi - seg * 11;
    int n    = nt * 8 + (lane >> 2);
    int k0   = c * 16 + (lane & 3) * 2;
    uint32_t out[2];
    #pragma unroll
    for (int half = 0; half < 2; half++) {
        float w0 = 0.f, w1 = 0.f;
        int ka = k0 + half * 8, kb = ka + 1;
        if (ka < KD) w0 = W[ka * OUTC + n];
        if (kb < KD) w1 = W[kb * OUTC + n];
        uint32_t hip;
        asm("cvt.rn.satfinite.bf16x2.f32 %0, %1, %2;" : "=r"(hip) : "f"(w1), "f"(w0));
        if (!seg) {
            out[half] = hip;
        } else {
            float h0 = __uint_as_float(hip << 16);
            float h1 = __uint_as_float(hip & 0xffff0000u);
            uint32_t lop;
            asm("cvt.rn.satfinite.bf16x2.f32 %0, %1, %2;"
                : "=r"(lop) : "f"(w1 - h1), "f"(w0 - h0));
            out[half] = lop;
        }
    }
    g_bfrag[idx] = make_uint2(out[0], out[1]);
}

// ------------------------- 2b. conv edge GEMM (mma.sync bf16 3-product) -----
__device__ __forceinline__ void gatherTile(uint32_t* sA, const float* __restrict__ ef,
                                           const int* __restrict__ ei, int nEdges,
                                           int t, int nTiles, int wid, int lane) {
    if (t >= nTiles) return;
    int e0 = t << 7;
    int qq = lane & 15;
    #pragma unroll 1
    for (int rr = 0; rr < 16; rr++) {
        int r = wid * 16 + rr;
        int e = e0 + r;
        bool valid = e < nEdges;
        uint32_t* row = sA + r * ASTRIDE;
        float4 v = make_float4(0.f, 0.f, 0.f, 0.f);
        if (valid) {
            int node = (lane < 16) ? ei[e] : ei[nEdges + e];
            v = ((const float4*)(g_h + (size_t)node * HDIM))[qq];
        }
        int c0 = ((lane < 16) ? 0 : 64) + qq * 4;
        put2(row, c0, v.x, v.y);
        put2(row, c0 + 2, v.z, v.w);
        if (lane < 21) {
            int kk = lane << 1;
            float f0 = 0.f, f1 = 0.f;
            if (valid) {
                const float* p = ef + (size_t)e * EDGE_DIM;
                f0 = p[kk];
                if (kk + 1 < EDGE_DIM) f1 = p[kk + 1];
            }
            put2(row, 2 * HDIM + kk, f0, f1);
        }
    }
}

__global__ void __launch_bounds__(256, 1)
conv_mma_kernel(const float* __restrict__ ef, const int* __restrict__ ei,
                int nEdges, int nTiles) {
    extern __shared__ uint32_t sm[];
    uint32_t* sA = sm;                          // [128][ASTRIDE]
    uint2*    sB = (uint2*)(sm + AWORDS);       // [NB][16][32]
    uint32_t* sZ = sm + AWORDS + 2 * BU2;       // [128][ZSTRIDE]

    const int tid = threadIdx.x, wid = tid >> 5, lane = tid & 31;
    const int q = lane & 3, r8 = lane >> 2;
    const int wm = wid & 3, wn = wid >> 2;

    for (int i = tid; i < AWORDS; i += 256) sA[i] = 0;
    for (int i = tid; i < BU2 / 2; i += 256)
        ((uint4*)sB)[i] = ((const uint4*)g_bfrag)[i];

    // BN stats accumulators: col pair cp = tid&63, rows [rseg*32, rseg*32+32)
    const int cp = tid & 63, rseg = tid >> 6;
    float st_s0 = 0.f, st_s1 = 0.f, st_q0 = 0.f, st_q1 = 0.f;

    gatherTile(sA, ef, ei, nEdges, blockIdx.x, nTiles, wid, lane);
    __syncthreads();

    for (int t = blockIdx.x; t < nTiles; t += gridDim.x) {
        // ---- MMA: 33 k-steps of m16n8k16 over warp tile 32x64 ----
        float acc[2][8][4];
        #pragma unroll
        for (int mt = 0; mt < 2; mt++)
            #pragma unroll
            for (int nt = 0; nt < 8; nt++)
                #pragma unroll
                for (int j = 0; j < 4; j++) acc[mt][nt][j] = 0.f;

        const uint32_t* aRow0 = sA + (wm * 32 + r8) * ASTRIDE;
        const uint2*    bBase = sB + (wn * 8) * 32 + lane;

        #pragma unroll 1
        for (int s = 0; s < NS; s++) {
            int ac = s - ((s >= 22) ? 22 : 0);
            int bi = s - ((s >= 11) ? 11 : 0);
            int aw = ac * 8 + q;
            uint32_t a[2][4];
            #pragma unroll
            for (int mt = 0; mt < 2; mt++) {
                const uint32_t* ar = aRow0 + mt * 16 * ASTRIDE;
                a[mt][0] = ar[aw];
                a[mt][1] = ar[8 * ASTRIDE + aw];
                a[mt][2] = ar[aw + 4];
                a[mt][3] = ar[8 * ASTRIDE + aw + 4];
            }
            const uint2* bp = bBase + bi * 16 * 32;
            #pragma unroll
            for (int nt = 0; nt < 8; nt++) {
                uint2 b = bp[nt * 32];
                mma16816(acc[0][nt], a[0], b);
                mma16816(acc[1][nt], a[1], b);
            }
        }

        // ---- epilogue: acc -> z smem (fp16), conflict-free ----
        #pragma unroll
        for (int mt = 0; mt < 2; mt++)
            #pragma unroll
            for (int half = 0; half < 2; half++) {
                int row = wm * 32 + mt * 16 + half * 8 + r8;
                uint32_t* zr = sZ + row * ZSTRIDE + wn * 32 + q;
                #pragma unroll
                for (int nt = 0; nt < 8; nt++) {
                    __half2 h = __floats2half2_rn(acc[mt][nt][half * 2],
                                                  acc[mt][nt][half * 2 + 1]);
                    zr[nt * 4] = *reinterpret_cast<uint32_t*>(&h);
                }
            }
        __syncthreads();

        // ---- copy z tile to global (coalesced) + fused BN stats ----
        const int e0 = t << 7;
        const int vrows = min(nEdges - e0, 128);
        uint4* zg = (uint4*)(g_zh + (size_t)e0 * OUTC);
        #pragma unroll
        for (int i = 0; i < 8; i++) {
            int j = i * 256 + tid;
            int row = j >> 4;
            if (row < vrows) {
                const uint4* src = (const uint4*)(sZ + row * ZSTRIDE + (j & 15) * 4);
                zg[j] = *src;
            }
        }
        {
            const uint32_t* zp = sZ + (rseg * 32) * ZSTRIDE + cp;
            #pragma unroll 8
            for (int rr = 0; rr < 32; rr++) {
                uint32_t w = zp[rr * ZSTRIDE];
                __half2 h = *reinterpret_cast<__half2*>(&w);
                float f0 = __low2float(h), f1 = __high2float(h);
                st_s0 += f0; st_q0 += f0 * f0;
                st_s1 += f1; st_q1 += f1 * f1;
            }
        }

        // ---- gather next tile (A reads all done before epilogue) ----
        gatherTile(sA, ef, ei, nEdges, t + gridDim.x, nTiles, wid, lane);
        __syncthreads();
    }

    atomicAdd(&g_sum[2 * cp],       st_s0);
    atomicAdd(&g_sum[2 * cp + 1],   st_s1);
    atomicAdd(&g_sumsq[2 * cp],     st_q0);
    atomicAdd(&g_sumsq[2 * cp + 1], st_q1);
}

// ------------------------- 3. BN coefficients (self-zeroing stats) ----------
__global__ void bn_coef_kernel(const float* __restrict__ gamma,
                               const float* __restrict__ beta, float invE) {
    int c = threadIdx.x;
    float s = g_sum[c], ss = g_sumsq[c];
    float mean = s * invE;
    float var  = fmaf(-mean, mean, ss * invE);
    float a    = gamma[c] * rsqrtf(var + BN_EPS);
    g_coef[c]        = a;
    g_coef[OUTC + c] = fmaf(-mean, a, beta[c]);
    g_sum[c] = 0.f;
    g_sumsq[c] = 0.f;
}

// ------------------------- 4. gate + scatter-add (fp16 z) -------------------
__global__ void __launch_bounds__(256)
gate_scatter_kernel(const int* __restrict__ ei, int nEdges) {
    __shared__ float sc[2 * OUTC];
    sc[threadIdx.x] = g_coef[threadIdx.x];
    __syncthreads();
    long long gid = (long long)blockIdx.x * 256 + threadIdx.x;
    int e = (int)(gid >> 5);
    if (e >= nEdges) return;
    int l = threadIdx.x & 31;
    int s = ei[e];
    const __half* zr = g_zh + (size_t)e * OUTC;
    __half2 za = *(const __half2*)(zr + 2 * l);
    __half2 zb = *(const __half2*)(zr + 64 + 2 * l);
    float n0 = fmaf(__low2float(za),  sc[2 * l],     sc[OUTC + 2 * l]);
    float n1 = fmaf(__high2float(za), sc[2 * l + 1], sc[OUTC + 2 * l + 1]);
    float b0 = fmaf(__low2float(zb),  sc[64 + 2 * l],     sc[OUTC + 64 + 2 * l]);
    float b1 = fmaf(__high2float(zb), sc[64 + 2 * l + 1], sc[OUTC + 64 + 2 * l + 1]);
    float m0 = sigmoidf(n0) * softplusf(b0);
    float m1 = sigmoidf(n1) * softplusf(b1);
    float* hr = g_h + (size_t)s * HDIM;
    atomicAdd(hr + 2 * l, m0);
    atomicAdd(hr + 2 * l + 1, m1);
}

// ------------------------- 5. graph mean pooling ----------------------------
__global__ void __launch_bounds__(256)
pool_kernel(const int* __restrict__ gidArr, int nNodes) {
    int gid = blockIdx.x * 256 + threadIdx.x;
    int n = gid >> 5;
    if (n >= nNodes) return;
    int lane = gid & 31;
    int g = gidArr[n];
    atomicAdd(&g_pool[(size_t)g * HDIM + lane],      g_h[(size_t)n * HDIM + lane]);
    atomicAdd(&g_pool[(size_t)g * HDIM + lane + 32], g_h[(size_t)n * HDIM + lane + 32]);
    if (lane == 0) atomicAdd(&g_cnt[g], 1.0f);
}

// ------------------------- 6. prediction head (self-zeroing pool) -----------
__global__ void __launch_bounds__(PRED_H)
head_kernel(const float* __restrict__ fcW, const float* __restrict__ fcb,
            const float* __restrict__ outW, const float* __restrict__ outb,
            float* __restrict__ out) {
    __shared__ float sp[HDIM];
    __shared__ float red[PRED_H];
    int g = blockIdx.x, t = threadIdx.x;
    if (t < HDIM) {
        float c = g_cnt[g];
        sp[t] = g_pool[(size_t)g * HDIM + t] / fmaxf(c, 1.0f);
    }
    __syncthreads();
    float acc = fcb[t];
    #pragma unroll
    for (int k = 0; k < HDIM; k++) acc = fmaf(sp[k], fcW[k * PRED_H + t], acc);
    red[t] = softplusf(acc) * outW[t];
    __syncthreads();
    for (int sft = PRED_H / 2; sft > 0; sft >>= 1) {
        if (t < sft) red[t] += red[t + sft];
        __syncthreads();
    }
    if (t == 0) out[g] = red[0] + outb[0];
    __syncthreads();
    if (t < HDIM) g_pool[(size_t)g * HDIM + t] = 0.f;
    if (t == HDIM) g_cnt[g] = 0.f;
}

// ------------------------- launch -------------------------------------------
extern "C" void kernel_launch(void* const* d_in, const int* in_sizes, int n_in,
                              void* d_out, int out_size) {
    const float* node_feats = (const float*)d_in[0];
    const int*   edge_index = (const int*)d_in[1];
    const float* edge_feats = (const float*)d_in[2];
    const int*   graph_id   = (const int*)d_in[3];
    const float* emb_W      = (const float*)d_in[4];
    const float* emb_b      = (const float*)d_in[5];
    const float* conv_W     = (const float*)d_in[6];
    // d_in[7] = conv_b: zeros; any constant bias cancels exactly in BN.
    const float* bn_gamma   = (const float*)d_in[8];
    const float* bn_beta    = (const float*)d_in[9];
    const float* fc_W       = (const float*)d_in[10];
    const float* fc_b       = (const float*)d_in[11];
    const float* out_W      = (const float*)d_in[12];
    const float* out_b      = (const float*)d_in[13];

    int nNodes  = in_sizes[0] / NODE_DIM;
    int nEdges  = in_sizes[1] / 2;
    int nConv   = in_sizes[6] / (KD * OUTC);

    int nsm = 148;
    cudaDeviceGetAttribute(&nsm, cudaDevAttrMultiProcessorCount, 0);

    size_t convSmem = (size_t)SMEM_WORDS * 4;   // 217088 B
    cudaFuncSetAttribute(conv_mma_kernel,
                         cudaFuncAttributeMaxDynamicSharedMemorySize, (int)convSmem);

    emb_kernel<<<2048, 256>>>(node_feats, emb_W, emb_b, nNodes);

    int nTiles = (nEdges + 127) / 128;
    float invE = 1.0f / (float)nEdges;
    for (int l = 0; l < nConv; l++) {
        bfrag_kernel<<<(BU2 + 255) / 256, 256>>>(conv_W + (size_t)l * KD * OUTC);
        conv_mma_kernel<<<nsm, 256, convSmem>>>(edge_feats, edge_index, nEdges, nTiles);
        bn_coef_kernel<<<1, OUTC>>>(bn_gamma + l * OUTC, bn_beta + l * OUTC, invE);
        int gblocks = (int)(((long long)nEdges * 32 + 255) / 256);
        gate_scatter_kernel<<<gblocks, 256>>>(edge_index, nEdges);
    }

    pool_kernel<<<(int)(((long long)nNodes * 32 + 255) / 256), 256>>>(graph_id, nNodes);
    head_kernel<<<out_size, PRED_H>>>(fc_W, fc_b, out_W, out_b, (float*)d_out);
}

// round 4
// speedup vs baseline: 2.1608x; 1.8972x over previous
#include <cuda_runtime.h>
#include <cuda_bf16.h>
#include <cuda_fp16.h>
#include <cstdint>

#define HDIM 64
#define NODE_DIM 92
#define EDGE_DIM 41
#define KD 169            // 2H + EDGE_DIM
#define OUTC 128          // 2H
#define PRED_H 128
#define BN_EPS 1e-5f
#define MAX_NODES 100000
#define MAX_EDGES 1600000
#define MAX_GRAPHS 4096

#define NB 22             // B k16-chunks: [0,11)=hi, [11,22)=lo
#define NS 33             // MMA k-steps per tile
#define ASTRIDE 180       // A smem row stride (u32 words)
#define AWORDS (128 * ASTRIDE)
#define BU2    (NB * 16 * 32)            // 11264 uint2 = 90112 B
#define ZSTRIDE 68
#define ZWORDS (128 * ZSTRIDE)
#define SMEM_WORDS (AWORDS + 2 * BU2 + ZWORDS)   // 217088 B

// ------------------------- device scratch ------------------------------------
__device__ float  g_h[MAX_NODES * HDIM];
__device__ __half g_zh[(size_t)MAX_EDGES * OUTC];
__device__ float  g_sum[OUTC];
__device__ float  g_sumsq[OUTC];
__device__ float  g_coef[2 * OUTC];
__device__ float  g_pool[MAX_GRAPHS * HDIM];
__device__ float  g_cnt[MAX_GRAPHS];
__device__ __align__(16) uint2    g_bfrag[BU2];
__device__ __align__(16) uint32_t g_hsplit[(size_t)MAX_NODES * 64];   // 32 hi + 32 lo words
__device__ __align__(16) uint32_t g_efsplit[(size_t)MAX_EDGES * 48];  // 24 hi + 24 lo words

// ------------------------- helpers ------------------------------------------
__device__ __forceinline__ float softplusf(float x) {
    return fmaxf(x, 0.f) + log1pf(expf(-fabsf(x)));
}
__device__ __forceinline__ float sigmoidf(float x) { return 1.f / (1.f + expf(-x)); }

__device__ __forceinline__ void mma16816(float* d, const uint32_t* a, uint2 b) {
    asm volatile("mma.sync.aligned.m16n8k16.row.col.f32.bf16.bf16.f32 "
                 "{%0,%1,%2,%3}, {%4,%5,%6,%7}, {%8,%9}, {%0,%1,%2,%3};"
                 : "+f"(d[0]), "+f"(d[1]), "+f"(d[2]), "+f"(d[3])
                 : "r"(a[0]), "r"(a[1]), "r"(a[2]), "r"(a[3]), "r"(b.x), "r"(b.y));
}

__device__ __forceinline__ uint32_t smem_u32(const void* p) {
    uint32_t a;
    asm("{ .reg .u64 t; cvta.to.shared.u64 t, %1; cvt.u32.u64 %0, t; }" : "=r"(a) : "l"(p));
    return a;
}
__device__ __forceinline__ void cp16(uint32_t dst, const void* src, int sz) {
    asm volatile("cp.async.cg.shared.global [%0], [%1], 16, %2;"
                 :: "r"(dst), "l"(src), "r"(sz) : "memory");
}
#define CP_COMMIT() asm volatile("cp.async.commit_group;" ::: "memory")
#define CP_WAIT0()  asm volatile("cp.async.wait_group 0;" ::: "memory")

// hi/lo bf16x2 split of two floats
__device__ __forceinline__ void split2(float f0, float f1, uint32_t& hip, uint32_t& lop) {
    asm("cvt.rn.satfinite.bf16x2.f32 %0, %1, %2;" : "=r"(hip) : "f"(f1), "f"(f0));
    float h0 = __uint_as_float(hip << 16);
    float h1 = __uint_as_float(hip & 0xffff0000u);
    asm("cvt.rn.satfinite.bf16x2.f32 %0, %1, %2;" : "=r"(lop) : "f"(f1 - h1), "f"(f0 - h0));
}

// ------------------------- 1. node embedding --------------------------------
__global__ void __launch_bounds__(256)
emb_kernel(const float* __restrict__ nf, const float* __restrict__ Wm,
           const float* __restrict__ b, int nNodes) {
    __shared__ float sW[NODE_DIM * HDIM];
    __shared__ float sXn[8][NODE_DIM];
    for (int i = threadIdx.x; i < NODE_DIM * HDIM; i += 256) sW[i] = Wm[i];
    __syncthreads();
    int wid = threadIdx.x >> 5, lane = threadIdx.x & 31;
    int gw = (blockIdx.x * 256 + threadIdx.x) >> 5;
    int nW = (gridDim.x * 256) >> 5;
    float b0 = b[lane], b1 = b[lane + 32];
    for (int n = gw; n < nNodes; n += nW) {
        __syncwarp();
        for (int k = lane; k < NODE_DIM; k += 32) sXn[wid][k] = nf[(size_t)n * NODE_DIM + k];
        __syncwarp();
        float a0 = b0, a1 = b1;
        #pragma unroll 4
        for (int k = 0; k < NODE_DIM; k++) {
            float xv = sXn[wid][k];
            a0 = fmaf(xv, sW[k * HDIM + lane], a0);
            a1 = fmaf(xv, sW[k * HDIM + lane + 32], a1);
        }
        g_h[(size_t)n * HDIM + lane] = a0;
        g_h[(size_t)n * HDIM + lane + 32] = a1;
    }
}

// ------------------------- 1b. pre-split h / edge feats ---------------------
__global__ void __launch_bounds__(256)
hsplit_kernel(int nNodes) {
    int idx = blockIdx.x * 256 + threadIdx.x;     // n*32 + w
    if (idx >= nNodes * 32) return;
    int n = idx >> 5, w = idx & 31;
    float2 v = ((const float2*)g_h)[idx];
    uint32_t hip, lop;
    split2(v.x, v.y, hip, lop);
    g_hsplit[(size_t)n * 64 + w]      = hip;
    g_hsplit[(size_t)n * 64 + 32 + w] = lop;
}

__global__ void __launch_bounds__(256)
efsplit_kernel(const float* __restrict__ ef, int nEdges) {
    long long idx = (long long)blockIdx.x * 256 + threadIdx.x;  // e*24 + w
    if (idx >= (long long)nEdges * 24) return;
    int w = (int)(idx % 24);
    long long e = idx / 24;
    int c = 2 * w;
    float f0 = 0.f, f1 = 0.f;
    if (c < EDGE_DIM)     f0 = ef[e * EDGE_DIM + c];
    if (c + 1 < EDGE_DIM) f1 = ef[e * EDGE_DIM + c + 1];
    uint32_t hip, lop;
    split2(f0, f1, hip, lop);
    g_efsplit[e * 48 + w]      = hip;
    g_efsplit[e * 48 + 24 + w] = lop;
}

// ------------------------- 2a. B fragment precompute -------------------------
__global__ void __launch_bounds__(256)
bfrag_kernel(const float* __restrict__ W) {
    int idx = blockIdx.x * 256 + threadIdx.x;
    if (idx >= BU2) return;
    int lane = idx & 31;
    int nt   = (idx >> 5) & 15;
    int bi   = idx >> 9;
    int seg  = bi >= 11;
    int c    = bi - seg * 11;
    int n    = nt * 8 + (lane >> 2);
    int k0   = c * 16 + (lane & 3) * 2;
    uint32_t out[2];
    #pragma unroll
    for (int half = 0; half < 2; half++) {
        float w0 = 0.f, w1 = 0.f;
        int ka = k0 + half * 8, kb = ka + 1;
        if (ka < KD) w0 = W[ka * OUTC + n];
        if (kb < KD) w1 = W[kb * OUTC + n];
        uint32_t hip, lop;
        split2(w0, w1, hip, lop);
        out[half] = seg ? lop : hip;
    }
    g_bfrag[idx] = make_uint2(out[0], out[1]);
}

// ------------------------- 2b. conv edge GEMM -------------------------------
// gather tile t into sA entirely via cp.async (pre-split operands, no math)
__device__ __forceinline__ void gatherAsync(uint32_t* sA, const int* __restrict__ ei,
                                            int nEdges, int t, int nTiles) {
    if (t >= nTiles) return;
    int j = threadIdx.x;
    int row = j >> 1, half = j & 1;
    int e = (t << 7) + row;
    bool valid = e < nEdges;
    int ec = valid ? e : 0;
    int sz = valid ? 16 : 0;
    int node = ei[half ? nEdges + ec : ec];
    const char* hs = (const char*)(g_hsplit + (size_t)node * 64);
    uint32_t* rw = sA + row * ASTRIDE;
    uint32_t dh = smem_u32(rw + half * 32);          // h hi -> words 0..31 / 32..63
    uint32_t dl = smem_u32(rw + 88 + half * 32);     // h lo -> words 88.. / 120..
    #pragma unroll
    for (int i = 0; i < 8; i++) cp16(dh + i * 16, hs + i * 16, sz);
    #pragma unroll
    for (int i = 0; i < 8; i++) cp16(dl + i * 16, hs + 128 + i * 16, sz);
    const char* es = (const char*)(g_efsplit + (size_t)ec * 48 + half * 24);
    uint32_t de = smem_u32(rw + (half ? 152 : 64));  // ef hi -> 64..87, lo -> 152..175
    #pragma unroll
    for (int i = 0; i < 6; i++) cp16(de + i * 16, es + i * 16, sz);
    CP_COMMIT();
}

__global__ void __launch_bounds__(256, 1)
conv_mma_kernel(const int* __restrict__ ei, int nEdges, int nTiles) {
    extern __shared__ uint32_t sm[];
    uint32_t* sA = sm;                          // [128][ASTRIDE]
    uint2*    sB = (uint2*)(sm + AWORDS);       // [NB][16][32]
    uint32_t* sZ = sm + AWORDS + 2 * BU2;       // [128][ZSTRIDE]

    const int tid = threadIdx.x, wid = tid >> 5, lane = tid & 31;
    const int q = lane & 3, r8 = lane >> 2;
    const int wm = wid & 3, wn = wid >> 2;

    gatherAsync(sA, ei, nEdges, blockIdx.x, nTiles);
    for (int i = tid; i < BU2 / 2; i += 256)
        ((uint4*)sB)[i] = ((const uint4*)g_bfrag)[i];

    const int cp = tid & 63, rseg = tid >> 6;
    float st_s0 = 0.f, st_s1 = 0.f, st_q0 = 0.f, st_q1 = 0.f;

    CP_WAIT0();
    __syncthreads();

    for (int t = blockIdx.x; t < nTiles; t += gridDim.x) {
        // ---- MMA: 33 k-steps over 32x64 warp tile ----
        float acc[2][8][4];
        #pragma unroll
        for (int mt = 0; mt < 2; mt++)
            #pragma unroll
            for (int nt = 0; nt < 8; nt++)
                #pragma unroll
                for (int jj = 0; jj < 4; jj++) acc[mt][nt][jj] = 0.f;

        const uint32_t* aRow0 = sA + (wm * 32 + r8) * ASTRIDE;
        const uint2*    bBase = sB + (wn * 8) * 32 + lane;

        #pragma unroll 1
        for (int s = 0; s < NS; s++) {
            int ac = s - ((s >= 22) ? 22 : 0);
            int bi = s - ((s >= 11) ? 11 : 0);
            int aw = ac * 8 + q;
            uint32_t a[2][4];
            #pragma unroll
            for (int mt = 0; mt < 2; mt++) {
                const uint32_t* ar = aRow0 + mt * 16 * ASTRIDE;
                a[mt][0] = ar[aw];
                a[mt][1] = ar[8 * ASTRIDE + aw];
                a[mt][2] = ar[aw + 4];
                a[mt][3] = ar[8 * ASTRIDE + aw + 4];
            }
            const uint2* bp = bBase + bi * 16 * 32;
            #pragma unroll
            for (int nt = 0; nt < 8; nt++) {
                uint2 b = bp[nt * 32];
                mma16816(acc[0][nt], a[0], b);
                mma16816(acc[1][nt], a[1], b);
            }
        }
        __syncthreads();                       // all A reads complete

        gatherAsync(sA, ei, nEdges, t + gridDim.x, nTiles);   // async prefetch

        // ---- epilogue: acc -> z smem (fp16) ----
        #pragma unroll
        for (int mt = 0; mt < 2; mt++)
            #pragma unroll
            for (int half = 0; half < 2; half++) {
                int row = wm * 32 + mt * 16 + half * 8 + r8;
                uint32_t* zr = sZ + row * ZSTRIDE + wn * 32 + q;
                #pragma unroll
                for (int nt = 0; nt < 8; nt++) {
                    __half2 h = __floats2half2_rn(acc[mt][nt][half * 2],
                                                  acc[mt][nt][half * 2 + 1]);
                    zr[nt * 4] = *reinterpret_cast<uint32_t*>(&h);
                }
            }
        __syncthreads();

        // ---- copy z tile to global + fused BN stats ----
        const int e0 = t << 7;
        const int vrows = min(nEdges - e0, 128);
        uint4* zg = (uint4*)(g_zh + (size_t)e0 * OUTC);
        #pragma unroll
        for (int i = 0; i < 8; i++) {
            int j = i * 256 + tid;
            int row = j >> 4;
            if (row < vrows)
                zg[j] = *(const uint4*)(sZ + row * ZSTRIDE + (j & 15) * 4);
        }
        {
            const uint32_t* zp = sZ + (rseg * 32) * ZSTRIDE + cp;
            #pragma unroll 8
            for (int rr = 0; rr < 32; rr++) {
                uint32_t w = zp[rr * ZSTRIDE];
                __half2 h = *reinterpret_cast<__half2*>(&w);
                float f0 = __low2float(h), f1 = __high2float(h);
                st_s0 += f0; st_q0 += f0 * f0;
                st_s1 += f1; st_q1 += f1 * f1;
            }
        }
        CP_WAIT0();
        __syncthreads();
    }

    atomicAdd(&g_sum[2 * cp],       st_s0);
    atomicAdd(&g_sum[2 * cp + 1],   st_s1);
    atomicAdd(&g_sumsq[2 * cp],     st_q0);
    atomicAdd(&g_sumsq[2 * cp + 1], st_q1);
}

// ------------------------- 3. BN coefficients (self-zeroing stats) ----------
__global__ void bn_coef_kernel(const float* __restrict__ gamma,
                               const float* __restrict__ beta, float invE) {
    int c = threadIdx.x;
    float s = g_sum[c], ss = g_sumsq[c];
    float mean = s * invE;
    float var  = fmaf(-mean, mean, ss * invE);
    float a    = gamma[c] * rsqrtf(var + BN_EPS);
    g_coef[c]        = a;
    g_coef[OUTC + c] = fmaf(-mean, a, beta[c]);
    g_sum[c] = 0.f;
    g_sumsq[c] = 0.f;
}

// ------------------------- 4. gate + scatter-add (fp16 z) -------------------
__global__ void __launch_bounds__(256)
gate_scatter_kernel(const int* __restrict__ ei, int nEdges) {
    __shared__ float sc[2 * OUTC];
    sc[threadIdx.x] = g_coef[threadIdx.x];
    __syncthreads();
    long long gid = (long long)blockIdx.x * 256 + threadIdx.x;
    int e = (int)(gid >> 5);
    if (e >= nEdges) return;
    int l = threadIdx.x & 31;
    int s = ei[e];
    const __half* zr = g_zh + (size_t)e * OUTC;
    __half2 za = *(const __half2*)(zr + 2 * l);
    __half2 zb = *(const __half2*)(zr + 64 + 2 * l);
    float n0 = fmaf(__low2float(za),  sc[2 * l],     sc[OUTC + 2 * l]);
    float n1 = fmaf(__high2float(za), sc[2 * l + 1], sc[OUTC + 2 * l + 1]);
    float b0 = fmaf(__low2float(zb),  sc[64 + 2 * l],     sc[OUTC + 64 + 2 * l]);
    float b1 = fmaf(__high2float(zb), sc[64 + 2 * l + 1], sc[OUTC + 64 + 2 * l + 1]);
    float m0 = sigmoidf(n0) * softplusf(b0);
    float m1 = sigmoidf(n1) * softplusf(b1);
    float* hr = g_h + (size_t)s * HDIM;
    atomicAdd(hr + 2 * l, m0);
    atomicAdd(hr + 2 * l + 1, m1);
}

// ------------------------- 5. graph mean pooling ----------------------------
__global__ void __launch_bounds__(256)
pool_kernel(const int* __restrict__ gidArr, int nNodes) {
    int gid = blockIdx.x * 256 + threadIdx.x;
    int n = gid >> 5;
    if (n >= nNodes) return;
    int lane = gid & 31;
    int g = gidArr[n];
    atomicAdd(&g_pool[(size_t)g * HDIM + lane],      g_h[(size_t)n * HDIM + lane]);
    atomicAdd(&g_pool[(size_t)g * HDIM + lane + 32], g_h[(size_t)n * HDIM + lane + 32]);
    if (lane == 0) atomicAdd(&g_cnt[g], 1.0f);
}

// ------------------------- 6. prediction head (self-zeroing pool) -----------
__global__ void __launch_bounds__(PRED_H)
head_kernel(const float* __restrict__ fcW, const float* __restrict__ fcb,
            const float* __restrict__ outW, const float* __restrict__ outb,
            float* __restrict__ out) {
    __shared__ float sp[HDIM];
    __shared__ float red[PRED_H];
    int g = blockIdx.x, t = threadIdx.x;
    if (t < HDIM) {
        float c = g_cnt[g];
        sp[t] = g_pool[(size_t)g * HDIM + t] / fmaxf(c, 1.0f);
    }
    __syncthreads();
    float acc = fcb[t];
    #pragma unroll
    for (int k = 0; k < HDIM; k++) acc = fmaf(sp[k], fcW[k * PRED_H + t], acc);
    red[t] = softplusf(acc) * outW[t];
    __syncthreads();
    for (int sft = PRED_H / 2; sft > 0; sft >>= 1) {
        if (t < sft) red[t] += red[t + sft];
        __syncthreads();
    }
    if (t == 0) out[g] = red[0] + outb[0];
    __syncthreads();
    if (t < HDIM) g_pool[(size_t)g * HDIM + t] = 0.f;
    if (t == HDIM) g_cnt[g] = 0.f;
}

// ------------------------- launch -------------------------------------------
extern "C" void kernel_launch(void* const* d_in, const int* in_sizes, int n_in,
                              void* d_out, int out_size) {
    const float* node_feats = (const float*)d_in[0];
    const int*   edge_index = (const int*)d_in[1];
    const float* edge_feats = (const float*)d_in[2];
    const int*   graph_id   = (const int*)d_in[3];
    const float* emb_W      = (const float*)d_in[4];
    const float* emb_b      = (const float*)d_in[5];
    const float* conv_W     = (const float*)d_in[6];
    // d_in[7] = conv_b: zeros; constant bias cancels exactly in BN.
    const float* bn_gamma   = (const float*)d_in[8];
    const float* bn_beta    = (const float*)d_in[9];
    const float* fc_W       = (const float*)d_in[10];
    const float* fc_b       = (const float*)d_in[11];
    const float* out_W      = (const float*)d_in[12];
    const float* out_b      = (const float*)d_in[13];

    int nNodes  = in_sizes[0] / NODE_DIM;
    int nEdges  = in_sizes[1] / 2;
    int nConv   = in_sizes[6] / (KD * OUTC);

    int nsm = 148;
    cudaDeviceGetAttribute(&nsm, cudaDevAttrMultiProcessorCount, 0);

    size_t convSmem = (size_t)SMEM_WORDS * 4;
    cudaFuncSetAttribute(conv_mma_kernel,
                         cudaFuncAttributeMaxDynamicSharedMemorySize, (int)convSmem);

    emb_kernel<<<2048, 256>>>(node_feats, emb_W, emb_b, nNodes);
    {
        long long tot = (long long)nEdges * 24;
        efsplit_kernel<<<(int)((tot + 255) / 256), 256>>>(edge_feats, nEdges);
    }

    int nTiles = (nEdges + 127) / 128;
    float invE = 1.0f / (float)nEdges;
    for (int l = 0; l < nConv; l++) {
        bfrag_kernel<<<(BU2 + 255) / 256, 256>>>(conv_W + (size_t)l * KD * OUTC);
        hsplit_kernel<<<(nNodes * 32 + 255) / 256, 256>>>(nNodes);
        conv_mma_kernel<<<nsm, 256, convSmem>>>(edge_index, nEdges, nTiles);
        bn_coef_kernel<<<1, OUTC>>>(bn_gamma + l * OUTC, bn_beta + l * OUTC, invE);
        int gblocks = (int)(((long long)nEdges * 32 + 255) / 256);
        gate_scatter_kernel<<<gblocks, 256>>>(edge_index, nEdges);
    }

    pool_kernel<<<(int)(((long long)nNodes * 32 + 255) / 256), 256>>>(graph_id, nNodes);
    head_kernel<<<out_size, PRED_H>>>(fc_W, fc_b, out_W, out_b, (float*)d_out);
}

// round 5
// speedup vs baseline: 2.4719x; 1.1440x over previous
#include <cuda_runtime.h>
#include <cuda_bf16.h>
#include <cuda_fp16.h>
#include <cstdint>

#define HDIM 64
#define NODE_DIM 92
#define EDGE_DIM 41
#define KD 169            // 2H + EDGE_DIM
#define OUTC 128          // 2H
#define PRED_H 128
#define BN_EPS 1e-5f
#define MAX_NODES 100000
#define MAX_EDGES 1600000
#define MAX_GRAPHS 4096

#define NCH 11            // k16 chunks per limb product
#define ASTRIDE 180       // A smem row stride (u32 words): 176 data + 4 pad
#define AWORDS (128 * ASTRIDE)
#define BU2    (NCH * 16 * 32)           // 5632 uint2 = 45056 B (B hi-limb only)
#define SMEM_WORDS (2 * AWORDS + 2 * BU2)  // 229376 B

// ------------------------- device scratch ------------------------------------
__device__ float  g_h[MAX_NODES * HDIM];
__device__ __half g_zh[(size_t)MAX_EDGES * OUTC];
__device__ float  g_sum[OUTC];
__device__ float  g_sumsq[OUTC];
__device__ float  g_coef[2 * OUTC];
__device__ float  g_pool[MAX_GRAPHS * HDIM];
__device__ float  g_cnt[MAX_GRAPHS];
__device__ __align__(16) uint2    g_bfrag[BU2];
__device__ __align__(16) uint32_t g_hsplit[(size_t)MAX_NODES * 64];   // 32 hi + 32 lo words (fp16x2)
__device__ __align__(16) uint32_t g_efsplit[(size_t)MAX_EDGES * 48];  // 24 hi + 24 lo words

// ------------------------- helpers ------------------------------------------
__device__ __forceinline__ float softplusf(float x) {
    return fmaxf(x, 0.f) + log1pf(expf(-fabsf(x)));
}
__device__ __forceinline__ float sigmoidf(float x) { return 1.f / (1.f + expf(-x)); }

__device__ __forceinline__ void mma16816(float* d, const uint32_t* a, uint2 b) {
    asm volatile("mma.sync.aligned.m16n8k16.row.col.f32.f16.f16.f32 "
                 "{%0,%1,%2,%3}, {%4,%5,%6,%7}, {%8,%9}, {%0,%1,%2,%3};"
                 : "+f"(d[0]), "+f"(d[1]), "+f"(d[2]), "+f"(d[3])
                 : "r"(a[0]), "r"(a[1]), "r"(a[2]), "r"(a[3]), "r"(b.x), "r"(b.y));
}

__device__ __forceinline__ uint32_t smem_u32(const void* p) {
    uint32_t a;
    asm("{ .reg .u64 t; cvta.to.shared.u64 t, %1; cvt.u32.u64 %0, t; }" : "=r"(a) : "l"(p));
    return a;
}
__device__ __forceinline__ void cp16(uint32_t dst, const void* src, int sz) {
    asm volatile("cp.async.cg.shared.global [%0], [%1], 16, %2;"
                 :: "r"(dst), "l"(src), "r"(sz) : "memory");
}
#define CP_COMMIT() asm volatile("cp.async.commit_group;" ::: "memory")
#define CP_WAIT0()  asm volatile("cp.async.wait_group 0;" ::: "memory")

// fp16 hi/lo limb split of two floats
__device__ __forceinline__ void split2h(float f0, float f1, uint32_t& hip, uint32_t& lop) {
    __half2 h = __floats2half2_rn(f0, f1);
    float2 hf = __half22float2(h);
    __half2 l = __floats2half2_rn(f0 - hf.x, f1 - hf.y);
    hip = *reinterpret_cast<uint32_t*>(&h);
    lop = *reinterpret_cast<uint32_t*>(&l);
}

// ------------------------- 1. node embedding --------------------------------
__global__ void __launch_bounds__(256)
emb_kernel(const float* __restrict__ nf, const float* __restrict__ Wm,
           const float* __restrict__ b, int nNodes) {
    __shared__ float sW[NODE_DIM * HDIM];
    __shared__ float sXn[8][NODE_DIM];
    for (int i = threadIdx.x; i < NODE_DIM * HDIM; i += 256) sW[i] = Wm[i];
    __syncthreads();
    int wid = threadIdx.x >> 5, lane = threadIdx.x & 31;
    int gw = (blockIdx.x * 256 + threadIdx.x) >> 5;
    int nW = (gridDim.x * 256) >> 5;
    float b0 = b[lane], b1 = b[lane + 32];
    for (int n = gw; n < nNodes; n += nW) {
        __syncwarp();
        for (int k = lane; k < NODE_DIM; k += 32) sXn[wid][k] = nf[(size_t)n * NODE_DIM + k];
        __syncwarp();
        float a0 = b0, a1 = b1;
        #pragma unroll 4
        for (int k = 0; k < NODE_DIM; k++) {
            float xv = sXn[wid][k];
            a0 = fmaf(xv, sW[k * HDIM + lane], a0);
            a1 = fmaf(xv, sW[k * HDIM + lane + 32], a1);
        }
        g_h[(size_t)n * HDIM + lane] = a0;
        g_h[(size_t)n * HDIM + lane + 32] = a1;
    }
}

// ------------------------- 1b. pre-split h / edge feats ---------------------
__global__ void __launch_bounds__(256)
hsplit_kernel(int nNodes) {
    int idx = blockIdx.x * 256 + threadIdx.x;     // n*32 + w
    if (idx >= nNodes * 32) return;
    int n = idx >> 5, w = idx & 31;
    float2 v = ((const float2*)g_h)[idx];
    uint32_t hip, lop;
    split2h(v.x, v.y, hip, lop);
    g_hsplit[(size_t)n * 64 + w]      = hip;
    g_hsplit[(size_t)n * 64 + 32 + w] = lop;
}

__global__ void __launch_bounds__(256)
efsplit_kernel(const float* __restrict__ ef, int nEdges) {
    long long idx = (long long)blockIdx.x * 256 + threadIdx.x;  // e*24 + w
    if (idx >= (long long)nEdges * 24) return;
    int w = (int)(idx % 24);
    long long e = idx / 24;
    int c = 2 * w;
    float f0 = 0.f, f1 = 0.f;
    if (c < EDGE_DIM)     f0 = ef[e * EDGE_DIM + c];
    if (c + 1 < EDGE_DIM) f1 = ef[e * EDGE_DIM + c + 1];
    uint32_t hip, lop;
    split2h(f0, f1, hip, lop);
    g_efsplit[e * 48 + w]      = hip;
    g_efsplit[e * 48 + 24 + w] = lop;
}

// ------------------------- 2a. B fragment precompute (fp16 hi limb) ---------
__global__ void __launch_bounds__(256)
bfrag_kernel(const float* __restrict__ W) {
    int idx = blockIdx.x * 256 + threadIdx.x;
    if (idx >= BU2) return;
    int lane = idx & 31;
    int nt   = (idx >> 5) & 15;
    int bi   = idx >> 9;              // 0..10
    int n    = nt * 8 + (lane >> 2);
    int k0   = bi * 16 + (lane & 3) * 2;
    uint32_t out[2];
    #pragma unroll
    for (int half = 0; half < 2; half++) {
        float w0 = 0.f, w1 = 0.f;
        int ka = k0 + half * 8, kb = ka + 1;
        if (ka < KD) w0 = W[ka * OUTC + n];
        if (kb < KD) w1 = W[kb * OUTC + n];
        __half2 h = __floats2half2_rn(w0, w1);
        out[half] = *reinterpret_cast<uint32_t*>(&h);
    }
    g_bfrag[idx] = make_uint2(out[0], out[1]);
}

// ------------------------- 2b. conv edge GEMM -------------------------------
__device__ __forceinline__ void gatherAsync(uint32_t* sA, const int* __restrict__ ei,
                                            int nEdges, int t, int nTiles) {
    if (t >= nTiles) return;
    int j = threadIdx.x;
    int row = j >> 1, half = j & 1;
    int e = (t << 7) + row;
    bool valid = e < nEdges;
    int ec = valid ? e : 0;
    int sz = valid ? 16 : 0;
    int node = ei[half ? nEdges + ec : ec];
    const char* hs = (const char*)(g_hsplit + (size_t)node * 64);
    uint32_t* rw = sA + row * ASTRIDE;
    uint32_t dh = smem_u32(rw + half * 32);          // h hi -> words 0..63
    uint32_t dl = smem_u32(rw + 88 + half * 32);     // h lo -> words 88..151
    #pragma unroll
    for (int i = 0; i < 8; i++) cp16(dh + i * 16, hs + i * 16, sz);
    #pragma unroll
    for (int i = 0; i < 8; i++) cp16(dl + i * 16, hs + 128 + i * 16, sz);
    const char* es = (const char*)(g_efsplit + (size_t)ec * 48 + half * 24);
    uint32_t de = smem_u32(rw + (half ? 152 : 64));  // ef hi -> 64..87, lo -> 152..175
    #pragma unroll
    for (int i = 0; i < 6; i++) cp16(de + i * 16, es + i * 16, sz);
    CP_COMMIT();
}

__global__ void __launch_bounds__(256, 1)
conv_mma_kernel(const int* __restrict__ ei, int nEdges, int nTiles) {
    extern __shared__ uint32_t sm[];
    uint32_t* sA0 = sm;
    uint32_t* sA1 = sm + AWORDS;
    uint2*    sB  = (uint2*)(sm + 2 * AWORDS);      // [NCH][16][32]

    const int tid = threadIdx.x, wid = tid >> 5, lane = tid & 31;
    const int q = lane & 3, r8 = lane >> 2;
    const int wm = wid & 3, wn = wid >> 2;

    gatherAsync(sA0, ei, nEdges, blockIdx.x, nTiles);
    for (int i = tid; i < BU2 / 2; i += 256)
        ((uint4*)sB)[i] = ((const uint4*)g_bfrag)[i];

    float ssum[16], ssq[16];
    #pragma unroll
    for (int j = 0; j < 16; j++) { ssum[j] = 0.f; ssq[j] = 0.f; }

    CP_WAIT0();
    __syncthreads();

    int par = 0;
    for (int t = blockIdx.x; t < nTiles; t += gridDim.x) {
        uint32_t* cur = par ? sA1 : sA0;
        gatherAsync(par ? sA0 : sA1, ei, nEdges, t + gridDim.x, nTiles);

        // ---- MMA: 11 B-chunks, each applied to A-hi and A-lo limbs ----
        float acc[2][8][4];
        #pragma unroll
        for (int mt = 0; mt < 2; mt++)
            #pragma unroll
            for (int nt = 0; nt < 8; nt++)
                #pragma unroll
                for (int jj = 0; jj < 4; jj++) acc[mt][nt][jj] = 0.f;

        const uint32_t* aRow0 = cur + (wm * 32 + r8) * ASTRIDE;
        const uint2*    bBase = sB + (wn * 8) * 32 + lane;

        #pragma unroll 1
        for (int bi = 0; bi < NCH; bi++) {
            uint2 b[8];
            const uint2* bp = bBase + bi * 16 * 32;
            #pragma unroll
            for (int nt = 0; nt < 8; nt++) b[nt] = bp[nt * 32];
            uint32_t ah[2][4], al[2][4];
            int awh = bi * 8 + q, awl = (bi + NCH) * 8 + q;
            #pragma unroll
            for (int mt = 0; mt < 2; mt++) {
                const uint32_t* ar = aRow0 + mt * 16 * ASTRIDE;
                ah[mt][0] = ar[awh];               ah[mt][1] = ar[8 * ASTRIDE + awh];
                ah[mt][2] = ar[awh + 4];           ah[mt][3] = ar[8 * ASTRIDE + awh + 4];
                al[mt][0] = ar[awl];               al[mt][1] = ar[8 * ASTRIDE + awl];
                al[mt][2] = ar[awl + 4];           al[mt][3] = ar[8 * ASTRIDE + awl + 4];
            }
            #pragma unroll
            for (int nt = 0; nt < 8; nt++) {
                mma16816(acc[0][nt], ah[0], b[nt]);
                mma16816(acc[1][nt], ah[1], b[nt]);
                mma16816(acc[0][nt], al[0], b[nt]);
                mma16816(acc[1][nt], al[1], b[nt]);
            }
        }

        // ---- BN stats from fp32 accumulators (zero rows contribute 0) ----
        #pragma unroll
        for (int mt = 0; mt < 2; mt++)
            #pragma unroll
            for (int nt = 0; nt < 8; nt++) {
                float c0 = acc[mt][nt][0], c1 = acc[mt][nt][1];
                float c2 = acc[mt][nt][2], c3 = acc[mt][nt][3];
                ssum[2 * nt]     += c0 + c2;
                ssum[2 * nt + 1] += c1 + c3;
                ssq[2 * nt]      += c0 * c0 + c2 * c2;
                ssq[2 * nt + 1]  += c1 * c1 + c3 * c3;
            }

        // ---- epilogue: registers -> global z (fp16) ----
        const int e0 = t << 7;
        #pragma unroll
        for (int mt = 0; mt < 2; mt++)
            #pragma unroll
            for (int hf = 0; hf < 2; hf++) {
                int row = wm * 32 + mt * 16 + hf * 8 + r8;
                int e = e0 + row;
                if (e < nEdges) {
                    __half* base = g_zh + (size_t)e * OUTC + wn * 64 + 2 * q;
                    #pragma unroll
                    for (int nt = 0; nt < 8; nt++) {
                        __half2 h = __floats2half2_rn(acc[mt][nt][2 * hf],
                                                      acc[mt][nt][2 * hf + 1]);
                        *(uint32_t*)(base + nt * 8) = *reinterpret_cast<uint32_t*>(&h);
                    }
                }
            }

        CP_WAIT0();
        __syncthreads();
        par ^= 1;
    }

    // ---- finalize BN stats: reduce over the 8 lanes sharing q ----
    #pragma unroll
    for (int j = 0; j < 16; j++) {
        #pragma unroll
        for (int ofs = 4; ofs < 32; ofs <<= 1) {
            ssum[j] += __shfl_xor_sync(0xffffffffu, ssum[j], ofs);
            ssq[j]  += __shfl_xor_sync(0xffffffffu, ssq[j], ofs);
        }
    }
    if (lane < 4) {
        #pragma unroll
        for (int nt = 0; nt < 8; nt++)
            #pragma unroll
            for (int jj = 0; jj < 2; jj++) {
                int col = wn * 64 + nt * 8 + 2 * lane + jj;
                atomicAdd(&g_sum[col],   ssum[2 * nt + jj]);
                atomicAdd(&g_sumsq[col], ssq[2 * nt + jj]);
            }
    }
}

// ------------------------- 3. BN coefficients (self-zeroing stats) ----------
__global__ void bn_coef_kernel(const float* __restrict__ gamma,
                               const float* __restrict__ beta, float invE) {
    int c = threadIdx.x;
    float s = g_sum[c], ss = g_sumsq[c];
    float mean = s * invE;
    float var  = fmaf(-mean, mean, ss * invE);
    float a    = gamma[c] * rsqrtf(var + BN_EPS);
    g_coef[c]        = a;
    g_coef[OUTC + c] = fmaf(-mean, a, beta[c]);
    g_sum[c] = 0.f;
    g_sumsq[c] = 0.f;
}

// ------------------------- 4. gate + scatter-add (fp16 z, v2 red) -----------
__global__ void __launch_bounds__(256)
gate_scatter_kernel(const int* __restrict__ ei, int nEdges) {
    __shared__ float sc[2 * OUTC];
    sc[threadIdx.x] = g_coef[threadIdx.x];
    __syncthreads();
    long long gid = (long long)blockIdx.x * 256 + threadIdx.x;
    int e = (int)(gid >> 5);
    if (e >= nEdges) return;
    int l = threadIdx.x & 31;
    int s = ei[e];
    const __half* zr = g_zh + (size_t)e * OUTC;
    __half2 za = *(const __half2*)(zr + 2 * l);
    __half2 zb = *(const __half2*)(zr + 64 + 2 * l);
    float n0 = fmaf(__low2float(za),  sc[2 * l],     sc[OUTC + 2 * l]);
    float n1 = fmaf(__high2float(za), sc[2 * l + 1], sc[OUTC + 2 * l + 1]);
    float b0 = fmaf(__low2float(zb),  sc[64 + 2 * l],     sc[OUTC + 64 + 2 * l]);
    float b1 = fmaf(__high2float(zb), sc[64 + 2 * l + 1], sc[OUTC + 64 + 2 * l + 1]);
    float m0 = sigmoidf(n0) * softplusf(b0);
    float m1 = sigmoidf(n1) * softplusf(b1);
    float* hr = g_h + (size_t)s * HDIM + 2 * l;
    asm volatile("red.global.add.v2.f32 [%0], {%1, %2};"
                 :: "l"(hr), "f"(m0), "f"(m1) : "memory");
}

// ------------------------- 5. graph mean pooling ----------------------------
__global__ void __launch_bounds__(256)
pool_kernel(const int* __restrict__ gidArr, int nNodes) {
    int gid = blockIdx.x * 256 + threadIdx.x;
    int n = gid >> 5;
    if (n >= nNodes) return;
    int lane = gid & 31;
    int g = gidArr[n];
    float2 v = ((const float2*)(g_h + (size_t)n * HDIM))[lane];
    float* pr = g_pool + (size_t)g * HDIM + 2 * lane;
    asm volatile("red.global.add.v2.f32 [%0], {%1, %2};"
                 :: "l"(pr), "f"(v.x), "f"(v.y) : "memory");
    if (lane == 0) atomicAdd(&g_cnt[g], 1.0f);
}

// ------------------------- 6. prediction head (self-zeroing pool) -----------
__global__ void __launch_bounds__(PRED_H)
head_kernel(const float* __restrict__ fcW, const float* __restrict__ fcb,
            const float* __restrict__ outW, const float* __restrict__ outb,
            float* __restrict__ out) {
    __shared__ float sp[HDIM];
    __shared__ float red[PRED_H];
    int g = blockIdx.x, t = threadIdx.x;
    if (t < HDIM) {
        float c = g_cnt[g];
        sp[t] = g_pool[(size_t)g * HDIM + t] / fmaxf(c, 1.0f);
    }
    __syncthreads();
    float acc = fcb[t];
    #pragma unroll
    for (int k = 0; k < HDIM; k++) acc = fmaf(sp[k], fcW[k * PRED_H + t], acc);
    red[t] = softplusf(acc) * outW[t];
    __syncthreads();
    for (int sft = PRED_H / 2; sft > 0; sft >>= 1) {
        if (t < sft) red[t] += red[t + sft];
        __syncthreads();
    }
    if (t == 0) out[g] = red[0] + outb[0];
    __syncthreads();
    if (t < HDIM) g_pool[(size_t)g * HDIM + t] = 0.f;
    if (t == HDIM) g_cnt[g] = 0.f;
}

// ------------------------- launch -------------------------------------------
extern "C" void kernel_launch(void* const* d_in, const int* in_sizes, int n_in,
                              void* d_out, int out_size) {
    const float* node_feats = (const float*)d_in[0];
    const int*   edge_index = (const int*)d_in[1];
    const float* edge_feats = (const float*)d_in[2];
    const int*   graph_id   = (const int*)d_in[3];
    const float* emb_W      = (const float*)d_in[4];
    const float* emb_b      = (const float*)d_in[5];
    const float* conv_W     = (const float*)d_in[6];
    // d_in[7] = conv_b: zeros; constant bias cancels exactly in BN.
    const float* bn_gamma   = (const float*)d_in[8];
    const float* bn_beta    = (const float*)d_in[9];
    const float* fc_W       = (const float*)d_in[10];
    const float* fc_b       = (const float*)d_in[11];
    const float* out_W      = (const float*)d_in[12];
    const float* out_b      = (const float*)d_in[13];

    int nNodes  = in_sizes[0] / NODE_DIM;
    int nEdges  = in_sizes[1] / 2;
    int nConv   = in_sizes[6] / (KD * OUTC);

    int nsm = 148;
    cudaDeviceGetAttribute(&nsm, cudaDevAttrMultiProcessorCount, 0);

    size_t convSmem = (size_t)SMEM_WORDS * 4;   // 229376 B
    cudaFuncSetAttribute(conv_mma_kernel,
                         cudaFuncAttributeMaxDynamicSharedMemorySize, (int)convSmem);

    emb_kernel<<<2048, 256>>>(node_feats, emb_W, emb_b, nNodes);
    {
        long long tot = (long long)nEdges * 24;
        efsplit_kernel<<<(int)((tot + 255) / 256), 256>>>(edge_feats, nEdges);
    }

    int nTiles = (nEdges + 127) / 128;
    float invE = 1.0f / (float)nEdges;
    for (int l = 0; l < nConv; l++) {
        bfrag_kernel<<<(BU2 + 255) / 256, 256>>>(conv_W + (size_t)l * KD * OUTC);
        hsplit_kernel<<<(nNodes * 32 + 255) / 256, 256>>>(nNodes);
        conv_mma_kernel<<<nsm, 256, convSmem>>>(edge_index, nEdges, nTiles);
        bn_coef_kernel<<<1, OUTC>>>(bn_gamma + l * OUTC, bn_beta + l * OUTC, invE);
        int gblocks = (int)(((long long)nEdges * 32 + 255) / 256);
        gate_scatter_kernel<<<gblocks, 256>>>(edge_index, nEdges);
    }

    pool_kernel<<<(int)(((long long)nNodes * 32 + 255) / 256), 256>>>(graph_id, nNodes);
    head_kernel<<<out_size, PRED_H>>>(fc_W, fc_b, out_W, out_b, (float*)d_out);
}

// round 6
// speedup vs baseline: 3.2179x; 1.3018x over previous
#include <cuda_runtime.h>
#include <cuda_bf16.h>
#include <cuda_fp16.h>
#include <cstdint>

#define HDIM 64
#define NODE_DIM 92
#define EDGE_DIM 41
#define KD 169            // 2H + EDGE_DIM
#define OUTC 128          // 2H
#define PRED_H 128
#define BN_EPS 1e-5f
#define MAX_NODES 100000
#define MAX_EDGES 1600000
#define MAX_GRAPHS 4096

#define NCH 11            // k16 chunks (K=176 padded)
#define ASTRIDE 92        // A smem row stride (u32 words): 88 data + 4 pad
#define AWORDS (128 * ASTRIDE)
#define BU2    (NCH * 16 * 32)               // 5632 uint2 = 45056 B
#define SMEM_WORDS (2 * AWORDS + 2 * BU2)    // 139264 B

// ------------------------- device scratch ------------------------------------
__device__ float  g_h[MAX_NODES * HDIM];
__device__ __half g_zh[(size_t)MAX_EDGES * OUTC];
__device__ float  g_sum[OUTC];
__device__ float  g_sumsq[OUTC];
__device__ float  g_coef[2 * OUTC];
__device__ float  g_pool[MAX_GRAPHS * HDIM];
__device__ float  g_cnt[MAX_GRAPHS];
__device__ __align__(16) uint2    g_bfrag[BU2];
__device__ __align__(16) uint32_t g_hh[(size_t)MAX_NODES * 32];   // h as fp16x2 (hi only)
__device__ __align__(16) uint32_t g_efh[(size_t)MAX_EDGES * 24];  // ef as fp16x2

// ------------------------- helpers ------------------------------------------
__device__ __forceinline__ float softplusf(float x) {
    return fmaxf(x, 0.f) + log1pf(expf(-fabsf(x)));
}
__device__ __forceinline__ float sigmoidf(float x) { return 1.f / (1.f + expf(-x)); }

__device__ __forceinline__ void mma16816(float* d, const uint32_t* a, uint2 b) {
    asm volatile("mma.sync.aligned.m16n8k16.row.col.f32.f16.f16.f32 "
                 "{%0,%1,%2,%3}, {%4,%5,%6,%7}, {%8,%9}, {%0,%1,%2,%3};"
                 : "+f"(d[0]), "+f"(d[1]), "+f"(d[2]), "+f"(d[3])
                 : "r"(a[0]), "r"(a[1]), "r"(a[2]), "r"(a[3]), "r"(b.x), "r"(b.y));
}

__device__ __forceinline__ uint32_t smem_u32(const void* p) {
    uint32_t a;
    asm("{ .reg .u64 t; cvta.to.shared.u64 t, %1; cvt.u32.u64 %0, t; }" : "=r"(a) : "l"(p));
    return a;
}
__device__ __forceinline__ void cp16(uint32_t dst, const void* src, int sz) {
    asm volatile("cp.async.cg.shared.global [%0], [%1], 16, %2;"
                 :: "r"(dst), "l"(src), "r"(sz) : "memory");
}
#define CP_COMMIT() asm volatile("cp.async.commit_group;" ::: "memory")
#define CP_WAIT0()  asm volatile("cp.async.wait_group 0;" ::: "memory")

// ------------------------- 1. node embedding --------------------------------
__global__ void __launch_bounds__(256)
emb_kernel(const float* __restrict__ nf, const float* __restrict__ Wm,
           const float* __restrict__ b, int nNodes) {
    __shared__ float sW[NODE_DIM * HDIM];
    __shared__ float sXn[8][NODE_DIM];
    for (int i = threadIdx.x; i < NODE_DIM * HDIM; i += 256) sW[i] = Wm[i];
    __syncthreads();
    int wid = threadIdx.x >> 5, lane = threadIdx.x & 31;
    int gw = (blockIdx.x * 256 + threadIdx.x) >> 5;
    int nW = (gridDim.x * 256) >> 5;
    float b0 = b[lane], b1 = b[lane + 32];
    for (int n = gw; n < nNodes; n += nW) {
        __syncwarp();
        for (int k = lane; k < NODE_DIM; k += 32) sXn[wid][k] = nf[(size_t)n * NODE_DIM + k];
        __syncwarp();
        float a0 = b0, a1 = b1;
        #pragma unroll 4
        for (int k = 0; k < NODE_DIM; k++) {
            float xv = sXn[wid][k];
            a0 = fmaf(xv, sW[k * HDIM + lane], a0);
            a1 = fmaf(xv, sW[k * HDIM + lane + 32], a1);
        }
        g_h[(size_t)n * HDIM + lane] = a0;
        g_h[(size_t)n * HDIM + lane + 32] = a1;
    }
}

// ------------------------- 1b. h / ef -> fp16 --------------------------------
__global__ void __launch_bounds__(256)
hsplit_kernel(int nNodes) {
    int idx = blockIdx.x * 256 + threadIdx.x;     // n*32 + w
    if (idx >= nNodes * 32) return;
    float2 v = ((const float2*)g_h)[idx];
    __half2 h = __floats2half2_rn(v.x, v.y);
    g_hh[idx] = *reinterpret_cast<uint32_t*>(&h);
}

__global__ void __launch_bounds__(256)
efsplit_kernel(const float* __restrict__ ef, int nEdges) {
    long long idx = (long long)blockIdx.x * 256 + threadIdx.x;  // e*24 + w
    if (idx >= (long long)nEdges * 24) return;
    int w = (int)(idx % 24);
    long long e = idx / 24;
    int c = 2 * w;
    float f0 = 0.f, f1 = 0.f;
    if (c < EDGE_DIM)     f0 = ef[e * EDGE_DIM + c];
    if (c + 1 < EDGE_DIM) f1 = ef[e * EDGE_DIM + c + 1];
    __half2 h = __floats2half2_rn(f0, f1);
    g_efh[idx] = *reinterpret_cast<uint32_t*>(&h);
}

// ------------------------- 2a. B fragment precompute (fp16) -----------------
__global__ void __launch_bounds__(256)
bfrag_kernel(const float* __restrict__ W) {
    int idx = blockIdx.x * 256 + threadIdx.x;
    if (idx >= BU2) return;
    int lane = idx & 31;
    int nt   = (idx >> 5) & 15;
    int bi   = idx >> 9;              // 0..10
    int n    = nt * 8 + (lane >> 2);
    int k0   = bi * 16 + (lane & 3) * 2;
    uint32_t out[2];
    #pragma unroll
    for (int half = 0; half < 2; half++) {
        float w0 = 0.f, w1 = 0.f;
        int ka = k0 + half * 8, kb = ka + 1;
        if (ka < KD) w0 = W[ka * OUTC + n];
        if (kb < KD) w1 = W[kb * OUTC + n];
        __half2 h = __floats2half2_rn(w0, w1);
        out[half] = *reinterpret_cast<uint32_t*>(&h);
    }
    g_bfrag[idx] = make_uint2(out[0], out[1]);
}

// ------------------------- 2b. conv edge GEMM -------------------------------
// A row layout (words): [0..31] src h, [32..63] dst h, [64..87] ef, stride 92
__device__ __forceinline__ void gatherAsync(uint32_t* sA, const int* __restrict__ ei,
                                            int nEdges, int t, int nTiles) {
    if (t >= nTiles) return;
    int j = threadIdx.x;
    int row = j >> 1, half = j & 1;
    int e = (t << 7) + row;
    bool valid = e < nEdges;
    int ec = valid ? e : 0;
    int sz = valid ? 16 : 0;
    int node = ei[half ? nEdges + ec : ec];
    const char* hs = (const char*)(g_hh + (size_t)node * 32);
    uint32_t* rw = sA + row * ASTRIDE;
    uint32_t dh = smem_u32(rw + half * 32);
    #pragma unroll
    for (int i = 0; i < 8; i++) cp16(dh + i * 16, hs + i * 16, sz);
    const char* es = (const char*)(g_efh + (size_t)ec * 24 + half * 12);
    uint32_t de = smem_u32(rw + 64 + half * 12);
    #pragma unroll
    for (int i = 0; i < 3; i++) cp16(de + i * 16, es + i * 16, sz);
    CP_COMMIT();
}

__global__ void __launch_bounds__(256, 1)
conv_mma_kernel(const int* __restrict__ ei, int nEdges, int nTiles) {
    extern __shared__ uint32_t sm[];
    uint32_t* sA0 = sm;
    uint32_t* sA1 = sm + AWORDS;
    uint2*    sB  = (uint2*)(sm + 2 * AWORDS);      // [NCH][16][32]

    const int tid = threadIdx.x, wid = tid >> 5, lane = tid & 31;
    const int q = lane & 3, r8 = lane >> 2;
    const int wm = wid & 3, wn = wid >> 2;

    gatherAsync(sA0, ei, nEdges, blockIdx.x, nTiles);
    for (int i = tid; i < BU2 / 2; i += 256)
        ((uint4*)sB)[i] = ((const uint4*)g_bfrag)[i];

    float ssum[16], ssq[16];
    #pragma unroll
    for (int j = 0; j < 16; j++) { ssum[j] = 0.f; ssq[j] = 0.f; }

    CP_WAIT0();
    __syncthreads();

    int par = 0;
    for (int t = blockIdx.x; t < nTiles; t += gridDim.x) {
        uint32_t* cur = par ? sA1 : sA0;
        gatherAsync(par ? sA0 : sA1, ei, nEdges, t + gridDim.x, nTiles);

        float acc[2][8][4];
        #pragma unroll
        for (int mt = 0; mt < 2; mt++)
            #pragma unroll
            for (int nt = 0; nt < 8; nt++)
                #pragma unroll
                for (int jj = 0; jj < 4; jj++) acc[mt][nt][jj] = 0.f;

        const uint32_t* aRow0 = cur + (wm * 32 + r8) * ASTRIDE;
        const uint2*    bBase = sB + (wn * 8) * 32 + lane;

        #pragma unroll 1
        for (int bi = 0; bi < NCH; bi++) {
            uint2 b[8];
            const uint2* bp = bBase + bi * 16 * 32;
            #pragma unroll
            for (int nt = 0; nt < 8; nt++) b[nt] = bp[nt * 32];
            uint32_t a[2][4];
            int aw = bi * 8 + q;
            #pragma unroll
            for (int mt = 0; mt < 2; mt++) {
                const uint32_t* ar = aRow0 + mt * 16 * ASTRIDE;
                a[mt][0] = ar[aw];         a[mt][1] = ar[8 * ASTRIDE + aw];
                a[mt][2] = ar[aw + 4];     a[mt][3] = ar[8 * ASTRIDE + aw + 4];
            }
            #pragma unroll
            for (int nt = 0; nt < 8; nt++) {
                mma16816(acc[0][nt], a[0], b[nt]);
                mma16816(acc[1][nt], a[1], b[nt]);
            }
        }

        // ---- BN stats from fp32 accumulators (zero rows contribute 0) ----
        #pragma unroll
        for (int mt = 0; mt < 2; mt++)
            #pragma unroll
            for (int nt = 0; nt < 8; nt++) {
                float c0 = acc[mt][nt][0], c1 = acc[mt][nt][1];
                float c2 = acc[mt][nt][2], c3 = acc[mt][nt][3];
                ssum[2 * nt]     += c0 + c2;
                ssum[2 * nt + 1] += c1 + c3;
                ssq[2 * nt]      += c0 * c0 + c2 * c2;
                ssq[2 * nt + 1]  += c1 * c1 + c3 * c3;
            }

        // ---- epilogue: registers -> global z (fp16) ----
        const int e0 = t << 7;
        #pragma unroll
        for (int mt = 0; mt < 2; mt++)
            #pragma unroll
            for (int hf = 0; hf < 2; hf++) {
                int row = wm * 32 + mt * 16 + hf * 8 + r8;
                int e = e0 + row;
                if (e < nEdges) {
                    __half* base = g_zh + (size_t)e * OUTC + wn * 64 + 2 * q;
                    #pragma unroll
                    for (int nt = 0; nt < 8; nt++) {
                        __half2 h = __floats2half2_rn(acc[mt][nt][2 * hf],
                                                      acc[mt][nt][2 * hf + 1]);
                        *(uint32_t*)(base + nt * 8) = *reinterpret_cast<uint32_t*>(&h);
                    }
                }
            }

        CP_WAIT0();
        __syncthreads();
        par ^= 1;
    }

    // ---- finalize BN stats ----
    #pragma unroll
    for (int j = 0; j < 16; j++) {
        #pragma unroll
        for (int ofs = 4; ofs < 32; ofs <<= 1) {
            ssum[j] += __shfl_xor_sync(0xffffffffu, ssum[j], ofs);
            ssq[j]  += __shfl_xor_sync(0xffffffffu, ssq[j], ofs);
        }
    }
    if (lane < 4) {
        #pragma unroll
        for (int nt = 0; nt < 8; nt++)
            #pragma unroll
            for (int jj = 0; jj < 2; jj++) {
                int col = wn * 64 + nt * 8 + 2 * lane + jj;
                atomicAdd(&g_sum[col],   ssum[2 * nt + jj]);
                atomicAdd(&g_sumsq[col], ssq[2 * nt + jj]);
            }
    }
}

// ------------------------- 3. BN coefficients (self-zeroing stats) ----------
__global__ void bn_coef_kernel(const float* __restrict__ gamma,
                               const float* __restrict__ beta, float invE) {
    int c = threadIdx.x;
    float s = g_sum[c], ss = g_sumsq[c];
    float mean = s * invE;
    float var  = fmaf(-mean, mean, ss * invE);
    float a    = gamma[c] * rsqrtf(var + BN_EPS);
    g_coef[c]        = a;
    g_coef[OUTC + c] = fmaf(-mean, a, beta[c]);
    g_sum[c] = 0.f;
    g_sumsq[c] = 0.f;
}

// ------------------------- 4. gate + scatter-add (fp16 z, v2 red) -----------
__global__ void __launch_bounds__(256)
gate_scatter_kernel(const int* __restrict__ ei, int nEdges) {
    __shared__ float sc[2 * OUTC];
    sc[threadIdx.x] = g_coef[threadIdx.x];
    __syncthreads();
    long long gid = (long long)blockIdx.x * 256 + threadIdx.x;
    int e = (int)(gid >> 5);
    if (e >= nEdges) return;
    int l = threadIdx.x & 31;
    int s = ei[e];
    const __half* zr = g_zh + (size_t)e * OUTC;
    __half2 za = *(const __half2*)(zr + 2 * l);
    __half2 zb = *(const __half2*)(zr + 64 + 2 * l);
    float n0 = fmaf(__low2float(za),  sc[2 * l],     sc[OUTC + 2 * l]);
    float n1 = fmaf(__high2float(za), sc[2 * l + 1], sc[OUTC + 2 * l + 1]);
    float b0 = fmaf(__low2float(zb),  sc[64 + 2 * l],     sc[OUTC + 64 + 2 * l]);
    float b1 = fmaf(__high2float(zb), sc[64 + 2 * l + 1], sc[OUTC + 64 + 2 * l + 1]);
    float m0 = sigmoidf(n0) * softplusf(b0);
    float m1 = sigmoidf(n1) * softplusf(b1);
    float* hr = g_h + (size_t)s * HDIM + 2 * l;
    asm volatile("red.global.add.v2.f32 [%0], {%1, %2};"
                 :: "l"(hr), "f"(m0), "f"(m1) : "memory");
}

// ------------------------- 5. graph mean pooling ----------------------------
__global__ void __launch_bounds__(256)
pool_kernel(const int* __restrict__ gidArr, int nNodes) {
    int gid = blockIdx.x * 256 + threadIdx.x;
    int n = gid >> 5;
    if (n >= nNodes) return;
    int lane = gid & 31;
    int g = gidArr[n];
    float2 v = ((const float2*)(g_h + (size_t)n * HDIM))[lane];
    float* pr = g_pool + (size_t)g * HDIM + 2 * lane;
    asm volatile("red.global.add.v2.f32 [%0], {%1, %2};"
                 :: "l"(pr), "f"(v.x), "f"(v.y) : "memory");
    if (lane == 0) atomicAdd(&g_cnt[g], 1.0f);
}

// ------------------------- 6. prediction head (self-zeroing pool) -----------
__global__ void __launch_bounds__(PRED_H)
head_kernel(const float* __restrict__ fcW, const float* __restrict__ fcb,
            const float* __restrict__ outW, const float* __restrict__ outb,
            float* __restrict__ out) {
    __shared__ float sp[HDIM];
    __shared__ float red[PRED_H];
    int g = blockIdx.x, t = threadIdx.x;
    if (t < HDIM) {
        float c = g_cnt[g];
        sp[t] = g_pool[(size_t)g * HDIM + t] / fmaxf(c, 1.0f);
    }
    __syncthreads();
    float acc = fcb[t];
    #pragma unroll
    for (int k = 0; k < HDIM; k++) acc = fmaf(sp[k], fcW[k * PRED_H + t], acc);
    red[t] = softplusf(acc) * outW[t];
    __syncthreads();
    for (int sft = PRED_H / 2; sft > 0; sft >>= 1) {
        if (t < sft) red[t] += red[t + sft];
        __syncthreads();
    }
    if (t == 0) out[g] = red[0] + outb[0];
    __syncthreads();
    if (t < HDIM) g_pool[(size_t)g * HDIM + t] = 0.f;
    if (t == HDIM) g_cnt[g] = 0.f;
}

// ------------------------- launch -------------------------------------------
extern "C" void kernel_launch(void* const* d_in, const int* in_sizes, int n_in,
                              void* d_out, int out_size) {
    const float* node_feats = (const float*)d_in[0];
    const int*   edge_index = (const int*)d_in[1];
    const float* edge_feats = (const float*)d_in[2];
    const int*   graph_id   = (const int*)d_in[3];
    const float* emb_W      = (const float*)d_in[4];
    const float* emb_b      = (const float*)d_in[5];
    const float* conv_W     = (const float*)d_in[6];
    // d_in[7] = conv_b: zeros; constant bias cancels exactly in BN.
    const float* bn_gamma   = (const float*)d_in[8];
    const float* bn_beta    = (const float*)d_in[9];
    const float* fc_W       = (const float*)d_in[10];
    const float* fc_b       = (const float*)d_in[11];
    const float* out_W      = (const float*)d_in[12];
    const float* out_b      = (const float*)d_in[13];

    int nNodes  = in_sizes[0] / NODE_DIM;
    int nEdges  = in_sizes[1] / 2;
    int nConv   = in_sizes[6] / (KD * OUTC);

    int nsm = 148;
    cudaDeviceGetAttribute(&nsm, cudaDevAttrMultiProcessorCount, 0);

    size_t convSmem = (size_t)SMEM_WORDS * 4;   // 139264 B
    cudaFuncSetAttribute(conv_mma_kernel,
                         cudaFuncAttributeMaxDynamicSharedMemorySize, (int)convSmem);

    emb_kernel<<<2048, 256>>>(node_feats, emb_W, emb_b, nNodes);
    {
        long long tot = (long long)nEdges * 24;
        efsplit_kernel<<<(int)((tot + 255) / 256), 256>>>(edge_feats, nEdges);
    }

    int nTiles = (nEdges + 127) / 128;
    float invE = 1.0f / (float)nEdges;
    for (int l = 0; l < nConv; l++) {
        bfrag_kernel<<<(BU2 + 255) / 256, 256>>>(conv_W + (size_t)l * KD * OUTC);
        hsplit_kernel<<<(nNodes * 32 + 255) / 256, 256>>>(nNodes);
        conv_mma_kernel<<<nsm, 256, convSmem>>>(edge_index, nEdges, nTiles);
        bn_coef_kernel<<<1, OUTC>>>(bn_gamma + l * OUTC, bn_beta + l * OUTC, invE);
        int gblocks = (int)(((long long)nEdges * 32 + 255) / 256);
        gate_scatter_kernel<<<gblocks, 256>>>(edge_index, nEdges);
    }

    pool_kernel<<<(int)(((long long)nNodes * 32 + 255) / 256), 256>>>(graph_id, nNodes);
    head_kernel<<<out_size, PRED_H>>>(fc_W, fc_b, out_W, out_b, (float*)d_out);
}

// round 7
// speedup vs baseline: 4.0535x; 1.2597x over previous
#include <cuda_runtime.h>
#include <cuda_bf16.h>
#include <cuda_fp16.h>
#include <cstdint>

#define HDIM 64
#define NODE_DIM 92
#define EDGE_DIM 41
#define KD 169            // 2H + EDGE_DIM
#define OUTC 128          // 2H
#define PRED_H 128
#define BN_EPS 1e-5f
#define MAX_NODES 100000
#define MAX_EDGES 1600000
#define MAX_GRAPHS 4096

#define NCH 11            // k16 chunks (K=176 padded)
#define ASTRIDE 92        // A smem row stride (u32 words): 88 data + 4 pad
#define AWORDS (128 * ASTRIDE)               // 11776 words = 47104 B
#define BU2    (NCH * 16 * 32)               // 5632 uint2 = 45056 B
#define SMEM_WORDS (AWORDS + 2 * BU2)        // 92160 B  -> 2 CTAs/SM

// ------------------------- device scratch ------------------------------------
__device__ float  g_h[MAX_NODES * HDIM];
__device__ __half g_zh[(size_t)MAX_EDGES * OUTC];
__device__ float  g_sum[OUTC];
__device__ float  g_sumsq[OUTC];
__device__ float  g_coef[2 * OUTC];
__device__ float  g_pool[MAX_GRAPHS * HDIM];
__device__ float  g_cnt[MAX_GRAPHS];
__device__ __align__(16) uint2    g_bfrag[BU2];
__device__ __align__(16) uint32_t g_hh[(size_t)MAX_NODES * 32];   // h as fp16x2
__device__ __align__(16) uint32_t g_efh[(size_t)MAX_EDGES * 24];  // ef as fp16x2
// CSR
__device__ int g_rowstart[MAX_NODES + 1];
__device__ int g_cursor[MAX_NODES];
__device__ int g_eidx[MAX_EDGES];
__device__ int g_bsum[1024];

// ------------------------- helpers ------------------------------------------
__device__ __forceinline__ float fsig(float x) {
    float t = __expf(-x);
    return __fdividef(1.f, 1.f + t);
}
__device__ __forceinline__ float fsp(float x) {
    float t = __expf(-fabsf(x));
    return fmaxf(x, 0.f) + __logf(1.f + t);
}

__device__ __forceinline__ void mma16816(float* d, const uint32_t* a, uint2 b) {
    asm volatile("mma.sync.aligned.m16n8k16.row.col.f32.f16.f16.f32 "
                 "{%0,%1,%2,%3}, {%4,%5,%6,%7}, {%8,%9}, {%0,%1,%2,%3};"
                 : "+f"(d[0]), "+f"(d[1]), "+f"(d[2]), "+f"(d[3])
                 : "r"(a[0]), "r"(a[1]), "r"(a[2]), "r"(a[3]), "r"(b.x), "r"(b.y));
}
__device__ __forceinline__ uint32_t smem_u32(const void* p) {
    uint32_t a;
    asm("{ .reg .u64 t; cvta.to.shared.u64 t, %1; cvt.u32.u64 %0, t; }" : "=r"(a) : "l"(p));
    return a;
}
__device__ __forceinline__ void cp16(uint32_t dst, const void* src, int sz) {
    asm volatile("cp.async.cg.shared.global [%0], [%1], 16, %2;"
                 :: "r"(dst), "l"(src), "r"(sz) : "memory");
}
#define CP_COMMIT() asm volatile("cp.async.commit_group;" ::: "memory")
#define CP_WAIT0()  asm volatile("cp.async.wait_group 0;" ::: "memory")

// ------------------------- 1. node embedding --------------------------------
__global__ void __launch_bounds__(256)
emb_kernel(const float* __restrict__ nf, const float* __restrict__ Wm,
           const float* __restrict__ b, int nNodes) {
    __shared__ float sW[NODE_DIM * HDIM];
    __shared__ float sXn[8][NODE_DIM];
    for (int i = threadIdx.x; i < NODE_DIM * HDIM; i += 256) sW[i] = Wm[i];
    __syncthreads();
    int wid = threadIdx.x >> 5, lane = threadIdx.x & 31;
    int gw = (blockIdx.x * 256 + threadIdx.x) >> 5;
    int nW = (gridDim.x * 256) >> 5;
    float b0 = b[lane], b1 = b[lane + 32];
    for (int n = gw; n < nNodes; n += nW) {
        __syncwarp();
        for (int k = lane; k < NODE_DIM; k += 32) sXn[wid][k] = nf[(size_t)n * NODE_DIM + k];
        __syncwarp();
        float a0 = b0, a1 = b1;
        #pragma unroll 4
        for (int k = 0; k < NODE_DIM; k++) {
            float xv = sXn[wid][k];
            a0 = fmaf(xv, sW[k * HDIM + lane], a0);
            a1 = fmaf(xv, sW[k * HDIM + lane + 32], a1);
        }
        g_h[(size_t)n * HDIM + lane] = a0;
        g_h[(size_t)n * HDIM + lane + 32] = a1;
    }
}

// ------------------------- 1b. h / ef -> fp16 --------------------------------
__global__ void __launch_bounds__(256)
hsplit_kernel(int nNodes) {
    int idx = blockIdx.x * 256 + threadIdx.x;
    if (idx >= nNodes * 32) return;
    float2 v = ((const float2*)g_h)[idx];
    __half2 h = __floats2half2_rn(v.x, v.y);
    g_hh[idx] = *reinterpret_cast<uint32_t*>(&h);
}

__global__ void __launch_bounds__(256)
efsplit_kernel(const float* __restrict__ ef, int nEdges) {
    long long idx = (long long)blockIdx.x * 256 + threadIdx.x;
    if (idx >= (long long)nEdges * 24) return;
    int w = (int)(idx % 24);
    long long e = idx / 24;
    int c = 2 * w;
    float f0 = 0.f, f1 = 0.f;
    if (c < EDGE_DIM)     f0 = ef[e * EDGE_DIM + c];
    if (c + 1 < EDGE_DIM) f1 = ef[e * EDGE_DIM + c + 1];
    __half2 h = __floats2half2_rn(f0, f1);
    g_efh[idx] = *reinterpret_cast<uint32_t*>(&h);
}

// ------------------------- CSR build -----------------------------------------
__global__ void zero_cnt_kernel(int nNodes) {
    int i = blockIdx.x * 256 + threadIdx.x;
    if (i < nNodes) g_cursor[i] = 0;
}
__global__ void hist_kernel(const int* __restrict__ ei, int nEdges) {
    int e = blockIdx.x * 256 + threadIdx.x;
    if (e < nEdges) atomicAdd(&g_cursor[ei[e]], 1);
}
__global__ void __launch_bounds__(1024)
scan1_kernel(int n) {
    __shared__ int wsum[32];
    int tid = threadIdx.x;
    int i = blockIdx.x * 1024 + tid;
    int c = (i < n) ? g_cursor[i] : 0;
    int v = c;
    #pragma unroll
    for (int o = 1; o < 32; o <<= 1) {
        int t = __shfl_up_sync(0xffffffffu, v, o);
        if ((tid & 31) >= o) v += t;
    }
    if ((tid & 31) == 31) wsum[tid >> 5] = v;
    __syncthreads();
    if (tid < 32) {
        int s = wsum[tid];
        #pragma unroll
        for (int o = 1; o < 32; o <<= 1) {
            int t = __shfl_up_sync(0xffffffffu, s, o);
            if (tid >= o) s += t;
        }
        wsum[tid] = s;
    }
    __syncthreads();
    int incl = v + ((tid >= 32) ? wsum[(tid >> 5) - 1] : 0);
    if (i < n) g_rowstart[i] = incl - c;           // block-local exclusive
    if (tid == 1023) g_bsum[blockIdx.x] = incl;    // block total
}
__global__ void __launch_bounds__(1024)
scan2_kernel(int nb) {
    __shared__ int wsum[32];
    int tid = threadIdx.x;
    int v = (tid < nb) ? g_bsum[tid] : 0;
    #pragma unroll
    for (int o = 1; o < 32; o <<= 1) {
        int t = __shfl_up_sync(0xffffffffu, v, o);
        if ((tid & 31) >= o) v += t;
    }
    if ((tid & 31) == 31) wsum[tid >> 5] = v;
    __syncthreads();
    if (tid < 32) {
        int s = wsum[tid];
        #pragma unroll
        for (int o = 1; o < 32; o <<= 1) {
            int t = __shfl_up_sync(0xffffffffu, s, o);
            if (tid >= o) s += t;
        }
        wsum[tid] = s;
    }
    __syncthreads();
    int incl = v + ((tid >= 32) ? wsum[(tid >> 5) - 1] : 0);
    if (tid < nb) g_bsum[tid] = incl;
}
__global__ void __launch_bounds__(1024)
scan3_kernel(int n, int nEdges) {
    int i = blockIdx.x * 1024 + threadIdx.x;
    if (i >= n) return;
    int off = blockIdx.x ? g_bsum[blockIdx.x - 1] : 0;
    int ex = g_rowstart[i] + off;
    g_rowstart[i] = ex;
    g_cursor[i] = ex;
    if (i == n - 1) g_rowstart[n] = nEdges;
}
__global__ void scatter_kernel(const int* __restrict__ ei, int nEdges) {
    int e = blockIdx.x * 256 + threadIdx.x;
    if (e >= nEdges) return;
    int p = atomicAdd(&g_cursor[ei[e]], 1);
    g_eidx[p] = e;
}

// ------------------------- 2a. B fragment precompute (fp16) -----------------
__global__ void __launch_bounds__(256)
bfrag_kernel(const float* __restrict__ W) {
    int idx = blockIdx.x * 256 + threadIdx.x;
    if (idx >= BU2) return;
    int lane = idx & 31;
    int nt   = (idx >> 5) & 15;
    int bi   = idx >> 9;              // 0..10
    int n    = nt * 8 + (lane >> 2);
    int k0   = bi * 16 + (lane & 3) * 2;
    uint32_t out[2];
    #pragma unroll
    for (int half = 0; half < 2; half++) {
        float w0 = 0.f, w1 = 0.f;
        int ka = k0 + half * 8, kb = ka + 1;
        if (ka < KD) w0 = W[ka * OUTC + n];
        if (kb < KD) w1 = W[kb * OUTC + n];
        __half2 h = __floats2half2_rn(w0, w1);
        out[half] = *reinterpret_cast<uint32_t*>(&h);
    }
    g_bfrag[idx] = make_uint2(out[0], out[1]);
}

// ------------------------- 2b. conv edge GEMM (2 CTAs/SM, N-split) ----------
__device__ __forceinline__ void gatherAsync(uint32_t* sA, const int* __restrict__ ei,
                                            int nEdges, int t, int nTiles) {
    if (t >= nTiles) return;
    int j = threadIdx.x;
    int row = j >> 1, half = j & 1;
    int e = (t << 7) + row;
    bool valid = e < nEdges;
    int ec = valid ? e : 0;
    int sz = valid ? 16 : 0;
    int node = ei[half ? nEdges + ec : ec];
    const char* hs = (const char*)(g_hh + (size_t)node * 32);
    uint32_t* rw = sA + row * ASTRIDE;
    uint32_t dh = smem_u32(rw + half * 32);
    #pragma unroll
    for (int i = 0; i < 8; i++) cp16(dh + i * 16, hs + i * 16, sz);
    const char* es = (const char*)(g_efh + (size_t)ec * 24 + half * 12);
    uint32_t de = smem_u32(rw + 64 + half * 12);
    #pragma unroll
    for (int i = 0; i < 3; i++) cp16(de + i * 16, es + i * 16, sz);
    CP_COMMIT();
}

__device__ __forceinline__ void kloop(float acc[2][4][4], const uint32_t* aRow0,
                                      const uint2* bBase, int nh, int q) {
    #pragma unroll 1
    for (int bi = 0; bi < NCH; bi++) {
        uint2 b[4];
        const uint2* bp = bBase + bi * 512 + nh * 128;
        #pragma unroll
        for (int n4 = 0; n4 < 4; n4++) b[n4] = bp[n4 * 32];
        uint32_t a[2][4];
        int aw = bi * 8 + q;
        #pragma unroll
        for (int mt = 0; mt < 2; mt++) {
            const uint32_t* ar = aRow0 + mt * 16 * ASTRIDE;
            a[mt][0] = ar[aw];         a[mt][1] = ar[8 * ASTRIDE + aw];
            a[mt][2] = ar[aw + 4];     a[mt][3] = ar[8 * ASTRIDE + aw + 4];
        }
        #pragma unroll
        for (int n4 = 0; n4 < 4; n4++) {
            mma16816(acc[0][n4], a[0], b[n4]);
            mma16816(acc[1][n4], a[1], b[n4]);
        }
    }
}

__device__ __forceinline__ void statsEpi(float acc[2][4][4], int nh, int e0, int nEdges,
                                         int wm, int wn, int q, int r8,
                                         float* ssum, float* ssq) {
    #pragma unroll
    for (int mt = 0; mt < 2; mt++)
        #pragma unroll
        for (int n4 = 0; n4 < 4; n4++) {
            float c0 = acc[mt][n4][0], c1 = acc[mt][n4][1];
            float c2 = acc[mt][n4][2], c3 = acc[mt][n4][3];
            int s = nh * 8 + n4 * 2;
            ssum[s]     += c0 + c2;   ssum[s + 1] += c1 + c3;
            ssq[s]      += c0 * c0 + c2 * c2;
            ssq[s + 1]  += c1 * c1 + c3 * c3;
        }
    #pragma unroll
    for (int mt = 0; mt < 2; mt++)
        #pragma unroll
        for (int hf = 0; hf < 2; hf++) {
            int row = wm * 32 + mt * 16 + hf * 8 + r8;
            int e = e0 + row;
            if (e < nEdges) {
                __half* base = g_zh + (size_t)e * OUTC + wn * 64 + nh * 32 + 2 * q;
                #pragma unroll
                for (int n4 = 0; n4 < 4; n4++) {
                    __half2 h = __floats2half2_rn(acc[mt][n4][2 * hf],
                                                  acc[mt][n4][2 * hf + 1]);
                    *(uint32_t*)(base + n4 * 8) = *reinterpret_cast<uint32_t*>(&h);
                }
            }
        }
}

__global__ void __launch_bounds__(256, 2)
conv_mma_kernel(const int* __restrict__ ei, int nEdges, int nTiles) {
    extern __shared__ uint32_t sm[];
    uint32_t* sA = sm;
    uint2*    sB = (uint2*)(sm + AWORDS);

    const int tid = threadIdx.x, wid = tid >> 5, lane = tid & 31;
    const int q = lane & 3, r8 = lane >> 2;
    const int wm = wid & 3, wn = wid >> 2;

    gatherAsync(sA, ei, nEdges, blockIdx.x, nTiles);
    for (int i = tid; i < BU2 / 2; i += 256)
        ((uint4*)sB)[i] = ((const uint4*)g_bfrag)[i];

    float ssum[16], ssq[16];
    #pragma unroll
    for (int j = 0; j < 16; j++) { ssum[j] = 0.f; ssq[j] = 0.f; }

    CP_WAIT0();
    __syncthreads();

    const uint32_t* aRow0 = sA + (wm * 32 + r8) * ASTRIDE;
    const uint2*    bBase = sB + (wn * 8) * 32 + lane;

    for (int t = blockIdx.x; t < nTiles; t += gridDim.x) {
        const int e0 = t << 7;
        {   // half 0: MMA + stats + z write
            float acc[2][4][4];
            #pragma unroll
            for (int mt = 0; mt < 2; mt++)
                #pragma unroll
                for (int n4 = 0; n4 < 4; n4++)
                    #pragma unroll
                    for (int jj = 0; jj < 4; jj++) acc[mt][n4][jj] = 0.f;
            kloop(acc, aRow0, bBase, 0, q);
            statsEpi(acc, 0, e0, nEdges, wm, wn, q, r8, ssum, ssq);
        }
        {   // half 1: MMA, then prefetch next tile, then stats + z write
            float acc[2][4][4];
            #pragma unroll
            for (int mt = 0; mt < 2; mt++)
                #pragma unroll
                for (int n4 = 0; n4 < 4; n4++)
                    #pragma unroll
                    for (int jj = 0; jj < 4; jj++) acc[mt][n4][jj] = 0.f;
            kloop(acc, aRow0, bBase, 1, q);
            __syncthreads();                       // all A reads done
            gatherAsync(sA, ei, nEdges, t + gridDim.x, nTiles);
            statsEpi(acc, 1, e0, nEdges, wm, wn, q, r8, ssum, ssq);
        }
        CP_WAIT0();
        __syncthreads();
    }

    // ---- finalize BN stats ----
    #pragma unroll
    for (int j = 0; j < 16; j++) {
        #pragma unroll
        for (int ofs = 4; ofs < 32; ofs <<= 1) {
            ssum[j] += __shfl_xor_sync(0xffffffffu, ssum[j], ofs);
            ssq[j]  += __shfl_xor_sync(0xffffffffu, ssq[j], ofs);
        }
    }
    if (lane < 4) {
        #pragma unroll
        for (int nh = 0; nh < 2; nh++)
            #pragma unroll
            for (int n4 = 0; n4 < 4; n4++)
                #pragma unroll
                for (int jj = 0; jj < 2; jj++) {
                    int col = wn * 64 + nh * 32 + n4 * 8 + 2 * lane + jj;
                    atomicAdd(&g_sum[col],   ssum[nh * 8 + n4 * 2 + jj]);
                    atomicAdd(&g_sumsq[col], ssq[nh * 8 + n4 * 2 + jj]);
                }
    }
}

// ------------------------- 3. BN coefficients (self-zeroing stats) ----------
__global__ void bn_coef_kernel(const float* __restrict__ gamma,
                               const float* __restrict__ beta, float invE) {
    int c = threadIdx.x;
    float s = g_sum[c], ss = g_sumsq[c];
    float mean = s * invE;
    float var  = fmaf(-mean, mean, ss * invE);
    float a    = gamma[c] * rsqrtf(var + BN_EPS);
    g_coef[c]        = a;
    g_coef[OUTC + c] = fmaf(-mean, a, beta[c]);
    g_sum[c] = 0.f;
    g_sumsq[c] = 0.f;
}

// ------------------------- 4. CSR gate + gather-accumulate ------------------
// warp per node: atomic-free. Also refreshes g_hh; pools on last layer.
__global__ void __launch_bounds__(256)
csr_gate_kernel(const int* __restrict__ gidArr, int nNodes, int doPool) {
    int gw = blockIdx.x * 8 + (threadIdx.x >> 5);
    if (gw >= nNodes) return;
    int lane = threadIdx.x & 31;

    float sa0 = g_coef[2 * lane],            sa1 = g_coef[2 * lane + 1];
    float ha0 = g_coef[OUTC + 2 * lane],     ha1 = g_coef[OUTC + 2 * lane + 1];
    float sb0 = g_coef[64 + 2 * lane],       sb1 = g_coef[64 + 2 * lane + 1];
    float hb0 = g_coef[OUTC + 64 + 2 * lane], hb1 = g_coef[OUTC + 64 + 2 * lane + 1];

    int beg = g_rowstart[gw], end = g_rowstart[gw + 1];
    float a0 = 0.f, a1 = 0.f;
    for (int i = beg; i < end; i++) {
        int e = g_eidx[i];
        const uint32_t* zr = (const uint32_t*)(g_zh + (size_t)e * OUTC);
        uint32_t A = zr[lane], B = zr[32 + lane];
        __half2 ha = *reinterpret_cast<__half2*>(&A);
        __half2 hb = *reinterpret_cast<__half2*>(&B);
        float na0 = fmaf(__low2float(ha),  sa0, ha0);
        float na1 = fmaf(__high2float(ha), sa1, ha1);
        float nb0 = fmaf(__low2float(hb),  sb0, hb0);
        float nb1 = fmaf(__high2float(hb), sb1, hb1);
        a0 += fsig(na0) * fsp(nb0);
        a1 += fsig(na1) * fsp(nb1);
    }
    float2* hp = (float2*)(g_h + (size_t)gw * HDIM) + lane;
    float2 hv = *hp;
    hv.x += a0; hv.y += a1;
    *hp = hv;
    __half2 hh = __floats2half2_rn(hv.x, hv.y);
    g_hh[(size_t)gw * 32 + lane] = *reinterpret_cast<uint32_t*>(&hh);
    if (doPool) {
        int g = gidArr[gw];
        float* pr = g_pool + (size_t)g * HDIM + 2 * lane;
        asm volatile("red.global.add.v2.f32 [%0], {%1, %2};"
                     :: "l"(pr), "f"(hv.x), "f"(hv.y) : "memory");
        if (lane == 0) atomicAdd(&g_cnt[g], 1.0f);
    }
}

// ------------------------- 5. prediction head (self-zeroing pool) -----------
__global__ void __launch_bounds__(PRED_H)
head_kernel(const float* __restrict__ fcW, const float* __restrict__ fcb,
            const float* __restrict__ outW, const float* __restrict__ outb,
            float* __restrict__ out) {
    __shared__ float sp[HDIM];
    __shared__ float red[PRED_H];
    int g = blockIdx.x, t = threadIdx.x;
    if (t < HDIM) {
        float c = g_cnt[g];
        sp[t] = g_pool[(size_t)g * HDIM + t] / fmaxf(c, 1.0f);
    }
    __syncthreads();
    float acc = fcb[t];
    #pragma unroll
    for (int k = 0; k < HDIM; k++) acc = fmaf(sp[k], fcW[k * PRED_H + t], acc);
    red[t] = fmaxf(acc, 0.f) + log1pf(expf(-fabsf(acc)));
    red[t] *= outW[t];
    __syncthreads();
    for (int sft = PRED_H / 2; sft > 0; sft >>= 1) {
        if (t < sft) red[t] += red[t + sft];
        __syncthreads();
    }
    if (t == 0) out[g] = red[0] + outb[0];
    __syncthreads();
    if (t < HDIM) g_pool[(size_t)g * HDIM + t] = 0.f;
    if (t == HDIM) g_cnt[g] = 0.f;
}

// ------------------------- launch -------------------------------------------
extern "C" void kernel_launch(void* const* d_in, const int* in_sizes, int n_in,
                              void* d_out, int out_size) {
    const float* node_feats = (const float*)d_in[0];
    const int*   edge_index = (const int*)d_in[1];
    const float* edge_feats = (const float*)d_in[2];
    const int*   graph_id   = (const int*)d_in[3];
    const float* emb_W      = (const float*)d_in[4];
    const float* emb_b      = (const float*)d_in[5];
    const float* conv_W     = (const float*)d_in[6];
    // d_in[7] = conv_b: zeros; constant bias cancels exactly in BN.
    const float* bn_gamma   = (const float*)d_in[8];
    const float* bn_beta    = (const float*)d_in[9];
    const float* fc_W       = (const float*)d_in[10];
    const float* fc_b       = (const float*)d_in[11];
    const float* out_W      = (const float*)d_in[12];
    const float* out_b      = (const float*)d_in[13];

    int nNodes  = in_sizes[0] / NODE_DIM;
    int nEdges  = in_sizes[1] / 2;
    int nConv   = in_sizes[6] / (KD * OUTC);

    int nsm = 148;
    cudaDeviceGetAttribute(&nsm, cudaDevAttrMultiProcessorCount, 0);

    size_t convSmem = (size_t)SMEM_WORDS * 4;   // 92160 B
    cudaFuncSetAttribute(conv_mma_kernel,
                         cudaFuncAttributeMaxDynamicSharedMemorySize, (int)convSmem);

    emb_kernel<<<2048, 256>>>(node_feats, emb_W, emb_b, nNodes);
    hsplit_kernel<<<(nNodes * 32 + 255) / 256, 256>>>(nNodes);
    {
        long long tot = (long long)nEdges * 24;
        efsplit_kernel<<<(int)((tot + 255) / 256), 256>>>(edge_feats, nEdges);
    }

    // ---- CSR build (edge_index constant across layers) ----
    int eb = (nEdges + 255) / 256;
    int nb1 = (nNodes + 1023) / 1024;
    zero_cnt_kernel<<<(nNodes + 255) / 256, 256>>>(nNodes);
    hist_kernel<<<eb, 256>>>(edge_index, nEdges);
    scan1_kernel<<<nb1, 1024>>>(nNodes);
    scan2_kernel<<<1, 1024>>>(nb1);
    scan3_kernel<<<nb1, 1024>>>(nNodes, nEdges);
    scatter_kernel<<<eb, 256>>>(edge_index, nEdges);

    int nTiles = (nEdges + 127) / 128;
    float invE = 1.0f / (float)nEdges;
    int gateBlocks = (nNodes + 7) / 8;
    for (int l = 0; l < nConv; l++) {
        bfrag_kernel<<<(BU2 + 255) / 256, 256>>>(conv_W + (size_t)l * KD * OUTC);
        conv_mma_kernel<<<2 * nsm, 256, convSmem>>>(edge_index, nEdges, nTiles);
        bn_coef_kernel<<<1, OUTC>>>(bn_gamma + l * OUTC, bn_beta + l * OUTC, invE);
        csr_gate_kernel<<<gateBlocks, 256>>>(graph_id, nNodes, l == nConv - 1);
    }

    head_kernel<<<out_size, PRED_H>>>(fc_W, fc_b, out_W, out_b, (float*)d_out);
}

// round 8
// speedup vs baseline: 4.1121x; 1.0145x over previous
#include <cuda_runtime.h>
#include <cuda_bf16.h>
#include <cuda_fp16.h>
#include <cstdint>

#define HDIM 64
#define NODE_DIM 92
#define EDGE_DIM 41
#define KD 169            // 2H + EDGE_DIM
#define OUTC 128          // 2H
#define PRED_H 128
#define BN_EPS 1e-5f
#define MAX_NODES 100000
#define MAX_EDGES 1600000
#define MAX_GRAPHS 4096

#define NCH 11            // k16 chunks (K=176 padded)
#define ASTRIDE 92        // A smem row stride (u32 words): 88 data + 4 pad
#define AWORDS (128 * ASTRIDE)               // 47104 B
#define BU2    (NCH * 16 * 32)               // 5632 uint2 = 45056 B
#define SMEM_WORDS (AWORDS + 2 * BU2)        // 92160 B -> 2 CTAs/SM

// ------------------------- device scratch ------------------------------------
__device__ float  g_h[MAX_NODES * HDIM];
__device__ __half g_zh[(size_t)MAX_EDGES * OUTC];   // CSR-permuted pre-BN activations
__device__ float  g_sum[OUTC];
__device__ float  g_sumsq[OUTC];
__device__ float  g_coef[2 * OUTC];
__device__ float  g_pool[MAX_GRAPHS * HDIM];
__device__ float  g_cnt[MAX_GRAPHS];
__device__ __align__(16) uint2    g_bfrag[BU2];
__device__ __align__(16) uint32_t g_hh[(size_t)MAX_NODES * 32];   // h as fp16x2
__device__ __align__(16) uint32_t g_efh[(size_t)MAX_EDGES * 24];  // ef as fp16x2
// CSR
__device__ int g_rowstart[MAX_NODES + 1];
__device__ int g_cursor[MAX_NODES];
__device__ int g_epos[MAX_EDGES];                   // edge -> CSR position
__device__ int g_bsum[1024];

// ------------------------- helpers ------------------------------------------
__device__ __forceinline__ float fsig(float x) {
    float t = __expf(-x);
    return __fdividef(1.f, 1.f + t);
}
__device__ __forceinline__ float fsp(float x) {
    float t = __expf(-fabsf(x));
    return fmaxf(x, 0.f) + __logf(1.f + t);
}

__device__ __forceinline__ void mma16816(float* d, const uint32_t* a, uint2 b) {
    asm volatile("mma.sync.aligned.m16n8k16.row.col.f32.f16.f16.f32 "
                 "{%0,%1,%2,%3}, {%4,%5,%6,%7}, {%8,%9}, {%0,%1,%2,%3};"
                 : "+f"(d[0]), "+f"(d[1]), "+f"(d[2]), "+f"(d[3])
                 : "r"(a[0]), "r"(a[1]), "r"(a[2]), "r"(a[3]), "r"(b.x), "r"(b.y));
}
__device__ __forceinline__ uint32_t smem_u32(const void* p) {
    uint32_t a;
    asm("{ .reg .u64 t; cvta.to.shared.u64 t, %1; cvt.u32.u64 %0, t; }" : "=r"(a) : "l"(p));
    return a;
}
__device__ __forceinline__ void cp16(uint32_t dst, const void* src, int sz) {
    asm volatile("cp.async.cg.shared.global [%0], [%1], 16, %2;"
                 :: "r"(dst), "l"(src), "r"(sz) : "memory");
}
#define CP_COMMIT() asm volatile("cp.async.commit_group;" ::: "memory")
#define CP_WAIT0()  asm volatile("cp.async.wait_group 0;" ::: "memory")

// ------------------------- 1. node embedding --------------------------------
__global__ void __launch_bounds__(256)
emb_kernel(const float* __restrict__ nf, const float* __restrict__ Wm,
           const float* __restrict__ b, int nNodes) {
    __shared__ float sW[NODE_DIM * HDIM];
    __shared__ float sXn[8][NODE_DIM];
    for (int i = threadIdx.x; i < NODE_DIM * HDIM; i += 256) sW[i] = Wm[i];
    __syncthreads();
    int wid = threadIdx.x >> 5, lane = threadIdx.x & 31;
    int gw = (blockIdx.x * 256 + threadIdx.x) >> 5;
    int nW = (gridDim.x * 256) >> 5;
    float b0 = b[lane], b1 = b[lane + 32];
    for (int n = gw; n < nNodes; n += nW) {
        __syncwarp();
        for (int k = lane; k < NODE_DIM; k += 32) sXn[wid][k] = nf[(size_t)n * NODE_DIM + k];
        __syncwarp();
        float a0 = b0, a1 = b1;
        #pragma unroll 4
        for (int k = 0; k < NODE_DIM; k++) {
            float xv = sXn[wid][k];
            a0 = fmaf(xv, sW[k * HDIM + lane], a0);
            a1 = fmaf(xv, sW[k * HDIM + lane + 32], a1);
        }
        g_h[(size_t)n * HDIM + lane] = a0;
        g_h[(size_t)n * HDIM + lane + 32] = a1;
    }
}

// ------------------------- 1b. h / ef -> fp16 --------------------------------
__global__ void __launch_bounds__(256)
hsplit_kernel(int nNodes) {
    int idx = blockIdx.x * 256 + threadIdx.x;
    if (idx >= nNodes * 32) return;
    float2 v = ((const float2*)g_h)[idx];
    __half2 h = __floats2half2_rn(v.x, v.y);
    g_hh[idx] = *reinterpret_cast<uint32_t*>(&h);
}

__global__ void __launch_bounds__(256)
efsplit_kernel(const float* __restrict__ ef, int nEdges) {
    long long idx = (long long)blockIdx.x * 256 + threadIdx.x;
    if (idx >= (long long)nEdges * 24) return;
    int w = (int)(idx % 24);
    long long e = idx / 24;
    int c = 2 * w;
    float f0 = 0.f, f1 = 0.f;
    if (c < EDGE_DIM)     f0 = ef[e * EDGE_DIM + c];
    if (c + 1 < EDGE_DIM) f1 = ef[e * EDGE_DIM + c + 1];
    __half2 h = __floats2half2_rn(f0, f1);
    g_efh[idx] = *reinterpret_cast<uint32_t*>(&h);
}

// ------------------------- CSR build -----------------------------------------
__global__ void zero_cnt_kernel(int nNodes) {
    int i = blockIdx.x * 256 + threadIdx.x;
    if (i < nNodes) g_cursor[i] = 0;
}
__global__ void hist_kernel(const int* __restrict__ ei, int nEdges) {
    int e = blockIdx.x * 256 + threadIdx.x;
    if (e < nEdges) atomicAdd(&g_cursor[ei[e]], 1);
}
__global__ void __launch_bounds__(1024)
scan1_kernel(int n) {
    __shared__ int wsum[32];
    int tid = threadIdx.x;
    int i = blockIdx.x * 1024 + tid;
    int c = (i < n) ? g_cursor[i] : 0;
    int v = c;
    #pragma unroll
    for (int o = 1; o < 32; o <<= 1) {
        int t = __shfl_up_sync(0xffffffffu, v, o);
        if ((tid & 31) >= o) v += t;
    }
    if ((tid & 31) == 31) wsum[tid >> 5] = v;
    __syncthreads();
    if (tid < 32) {
        int s = wsum[tid];
        #pragma unroll
        for (int o = 1; o < 32; o <<= 1) {
            int t = __shfl_up_sync(0xffffffffu, s, o);
            if (tid >= o) s += t;
        }
        wsum[tid] = s;
    }
    __syncthreads();
    int incl = v + ((tid >= 32) ? wsum[(tid >> 5) - 1] : 0);
    if (i < n) g_rowstart[i] = incl - c;
    if (tid == 1023) g_bsum[blockIdx.x] = incl;
}
__global__ void __launch_bounds__(1024)
scan2_kernel(int nb) {
    __shared__ int wsum[32];
    int tid = threadIdx.x;
    int v = (tid < nb) ? g_bsum[tid] : 0;
    #pragma unroll
    for (int o = 1; o < 32; o <<= 1) {
        int t = __shfl_up_sync(0xffffffffu, v, o);
        if ((tid & 31) >= o) v += t;
    }
    if ((tid & 31) == 31) wsum[tid >> 5] = v;
    __syncthreads();
    if (tid < 32) {
        int s = wsum[tid];
        #pragma unroll
        for (int o = 1; o < 32; o <<= 1) {
            int t = __shfl_up_sync(0xffffffffu, s, o);
            if (tid >= o) s += t;
        }
        wsum[tid] = s;
    }
    __syncthreads();
    int incl = v + ((tid >= 32) ? wsum[(tid >> 5) - 1] : 0);
    if (tid < nb) g_bsum[tid] = incl;
}
__global__ void __launch_bounds__(1024)
scan3_kernel(int n, int nEdges) {
    int i = blockIdx.x * 1024 + threadIdx.x;
    if (i >= n) return;
    int off = blockIdx.x ? g_bsum[blockIdx.x - 1] : 0;
    int ex = g_rowstart[i] + off;
    g_rowstart[i] = ex;
    g_cursor[i] = ex;
    if (i == n - 1) g_rowstart[n] = nEdges;
}
__global__ void scatter_kernel(const int* __restrict__ ei, int nEdges) {
    int e = blockIdx.x * 256 + threadIdx.x;
    if (e >= nEdges) return;
    g_epos[e] = atomicAdd(&g_cursor[ei[e]], 1);
}

// ------------------------- 2a. B fragment precompute (fp16) -----------------
__global__ void __launch_bounds__(256)
bfrag_kernel(const float* __restrict__ W) {
    int idx = blockIdx.x * 256 + threadIdx.x;
    if (idx >= BU2) return;
    int lane = idx & 31;
    int nt   = (idx >> 5) & 15;
    int bi   = idx >> 9;              // 0..10
    int n    = nt * 8 + (lane >> 2);
    int k0   = bi * 16 + (lane & 3) * 2;
    uint32_t out[2];
    #pragma unroll
    for (int half = 0; half < 2; half++) {
        float w0 = 0.f, w1 = 0.f;
        int ka = k0 + half * 8, kb = ka + 1;
        if (ka < KD) w0 = W[ka * OUTC + n];
        if (kb < KD) w1 = W[kb * OUTC + n];
        __half2 h = __floats2half2_rn(w0, w1);
        out[half] = *reinterpret_cast<uint32_t*>(&h);
    }
    g_bfrag[idx] = make_uint2(out[0], out[1]);
}

// ------------------------- 2b. conv edge GEMM (2 CTAs/SM, N-split) ----------
__device__ __forceinline__ void gatherAsync(uint32_t* sA, const int* __restrict__ ei,
                                            int nEdges, int t, int nTiles) {
    if (t >= nTiles) return;
    int j = threadIdx.x;
    int row = j >> 1, half = j & 1;
    int e = (t << 7) + row;
    bool valid = e < nEdges;
    int ec = valid ? e : 0;
    int sz = valid ? 16 : 0;
    int node = ei[half ? nEdges + ec : ec];
    const char* hs = (const char*)(g_hh + (size_t)node * 32);
    uint32_t* rw = sA + row * ASTRIDE;
    uint32_t dh = smem_u32(rw + half * 32);
    #pragma unroll
    for (int i = 0; i < 8; i++) cp16(dh + i * 16, hs + i * 16, sz);
    const char* es = (const char*)(g_efh + (size_t)ec * 24 + half * 12);
    uint32_t de = smem_u32(rw + 64 + half * 12);
    #pragma unroll
    for (int i = 0; i < 3; i++) cp16(de + i * 16, es + i * 16, sz);
    CP_COMMIT();
}

__device__ __forceinline__ void kloop(float acc[2][4][4], const uint32_t* aRow0,
                                      const uint2* bBase, int nh, int q) {
    #pragma unroll 1
    for (int bi = 0; bi < NCH; bi++) {
        uint2 b[4];
        const uint2* bp = bBase + bi * 512 + nh * 128;
        #pragma unroll
        for (int n4 = 0; n4 < 4; n4++) b[n4] = bp[n4 * 32];
        uint32_t a[2][4];
        int aw = bi * 8 + q;
        #pragma unroll
        for (int mt = 0; mt < 2; mt++) {
            const uint32_t* ar = aRow0 + mt * 16 * ASTRIDE;
            a[mt][0] = ar[aw];         a[mt][1] = ar[8 * ASTRIDE + aw];
            a[mt][2] = ar[aw + 4];     a[mt][3] = ar[8 * ASTRIDE + aw + 4];
        }
        #pragma unroll
        for (int n4 = 0; n4 < 4; n4++) {
            mma16816(acc[0][n4], a[0], b[n4]);
            mma16816(acc[1][n4], a[1], b[n4]);
        }
    }
}

// epilogue: stats + z write to CSR-permuted rows (pe[mt*2+hf], -1 = invalid)
__device__ __forceinline__ void statsEpi(float acc[2][4][4], int nh, const int* pe,
                                         int wn, int q, float* ssum, float* ssq) {
    #pragma unroll
    for (int mt = 0; mt < 2; mt++)
        #pragma unroll
        for (int n4 = 0; n4 < 4; n4++) {
            float c0 = acc[mt][n4][0], c1 = acc[mt][n4][1];
            float c2 = acc[mt][n4][2], c3 = acc[mt][n4][3];
            int s = nh * 8 + n4 * 2;
            ssum[s]     += c0 + c2;   ssum[s + 1] += c1 + c3;
            ssq[s]      += c0 * c0 + c2 * c2;
            ssq[s + 1]  += c1 * c1 + c3 * c3;
        }
    #pragma unroll
    for (int mt = 0; mt < 2; mt++)
        #pragma unroll
        for (int hf = 0; hf < 2; hf++) {
            int p = pe[mt * 2 + hf];
            if (p >= 0) {
                __half* base = g_zh + (size_t)p * OUTC + wn * 64 + nh * 32 + 2 * q;
                #pragma unroll
                for (int n4 = 0; n4 < 4; n4++) {
                    __half2 h = __floats2half2_rn(acc[mt][n4][2 * hf],
                                                  acc[mt][n4][2 * hf + 1]);
                    *(uint32_t*)(base + n4 * 8) = *reinterpret_cast<uint32_t*>(&h);
                }
            }
        }
}

__global__ void __launch_bounds__(256, 2)
conv_mma_kernel(const int* __restrict__ ei, int nEdges, int nTiles) {
    extern __shared__ uint32_t sm[];
    uint32_t* sA = sm;
    uint2*    sB = (uint2*)(sm + AWORDS);

    const int tid = threadIdx.x, wid = tid >> 5, lane = tid & 31;
    const int q = lane & 3, r8 = lane >> 2;
    const int wm = wid & 3, wn = wid >> 2;

    gatherAsync(sA, ei, nEdges, blockIdx.x, nTiles);
    for (int i = tid; i < BU2 / 2; i += 256)
        ((uint4*)sB)[i] = ((const uint4*)g_bfrag)[i];

    float ssum[16], ssq[16];
    #pragma unroll
    for (int j = 0; j < 16; j++) { ssum[j] = 0.f; ssq[j] = 0.f; }

    CP_WAIT0();
    __syncthreads();

    const uint32_t* aRow0 = sA + (wm * 32 + r8) * ASTRIDE;
    const uint2*    bBase = sB + (wn * 8) * 32 + lane;

    for (int t = blockIdx.x; t < nTiles; t += gridDim.x) {
        const int e0 = t << 7;
        // CSR destinations for this thread's 4 output rows
        int pe[4];
        #pragma unroll
        for (int mt = 0; mt < 2; mt++)
            #pragma unroll
            for (int hf = 0; hf < 2; hf++) {
                int e = e0 + wm * 32 + mt * 16 + hf * 8 + r8;
                pe[mt * 2 + hf] = (e < nEdges) ? __ldg(&g_epos[e]) : -1;
            }
        {   // N half 0
            float acc[2][4][4];
            #pragma unroll
            for (int mt = 0; mt < 2; mt++)
                #pragma unroll
                for (int n4 = 0; n4 < 4; n4++)
                    #pragma unroll
                    for (int jj = 0; jj < 4; jj++) acc[mt][n4][jj] = 0.f;
            kloop(acc, aRow0, bBase, 0, q);
            statsEpi(acc, 0, pe, wn, q, ssum, ssq);
        }
        {   // N half 1 (+ prefetch next tile between MMA and epilogue)
            float acc[2][4][4];
            #pragma unroll
            for (int mt = 0; mt < 2; mt++)
                #pragma unroll
                for (int n4 = 0; n4 < 4; n4++)
                    #pragma unroll
                    for (int jj = 0; jj < 4; jj++) acc[mt][n4][jj] = 0.f;
            kloop(acc, aRow0, bBase, 1, q);
            __syncthreads();
            gatherAsync(sA, ei, nEdges, t + gridDim.x, nTiles);
            statsEpi(acc, 1, pe, wn, q, ssum, ssq);
        }
        CP_WAIT0();
        __syncthreads();
    }

    #pragma unroll
    for (int j = 0; j < 16; j++) {
        #pragma unroll
        for (int ofs = 4; ofs < 32; ofs <<= 1) {
            ssum[j] += __shfl_xor_sync(0xffffffffu, ssum[j], ofs);
            ssq[j]  += __shfl_xor_sync(0xffffffffu, ssq[j], ofs);
        }
    }
    if (lane < 4) {
        #pragma unroll
        for (int nh = 0; nh < 2; nh++)
            #pragma unroll
            for (int n4 = 0; n4 < 4; n4++)
                #pragma unroll
                for (int jj = 0; jj < 2; jj++) {
                    int col = wn * 64 + nh * 32 + n4 * 8 + 2 * lane + jj;
                    atomicAdd(&g_sum[col],   ssum[nh * 8 + n4 * 2 + jj]);
                    atomicAdd(&g_sumsq[col], ssq[nh * 8 + n4 * 2 + jj]);
                }
    }
}

// ------------------------- 3. BN coefficients (self-zeroing stats) ----------
__global__ void bn_coef_kernel(const float* __restrict__ gamma,
                               const float* __restrict__ beta, float invE) {
    int c = threadIdx.x;
    float s = g_sum[c], ss = g_sumsq[c];
    float mean = s * invE;
    float var  = fmaf(-mean, mean, ss * invE);
    float a    = gamma[c] * rsqrtf(var + BN_EPS);
    g_coef[c]        = a;
    g_coef[OUTC + c] = fmaf(-mean, a, beta[c]);
    g_sum[c] = 0.f;
    g_sumsq[c] = 0.f;
}

// ------------------------- 4. CSR gate: streaming z -------------------------
__global__ void __launch_bounds__(256)
csr_gate_kernel(const int* __restrict__ gidArr, int nNodes, int doPool) {
    int gw = blockIdx.x * 8 + (threadIdx.x >> 5);
    if (gw >= nNodes) return;
    int lane = threadIdx.x & 31;

    float sa0 = g_coef[2 * lane],             sa1 = g_coef[2 * lane + 1];
    float ha0 = g_coef[OUTC + 2 * lane],      ha1 = g_coef[OUTC + 2 * lane + 1];
    float sb0 = g_coef[64 + 2 * lane],        sb1 = g_coef[64 + 2 * lane + 1];
    float hb0 = g_coef[OUTC + 64 + 2 * lane], hb1 = g_coef[OUTC + 64 + 2 * lane + 1];

    int beg = g_rowstart[gw], end = g_rowstart[gw + 1];
    float a0 = 0.f, a1 = 0.f;
    const uint32_t* zr = (const uint32_t*)(g_zh) + (size_t)beg * 64;
    for (int i = beg; i < end; i++, zr += 64) {
        uint32_t A = zr[lane], B = zr[32 + lane];
        __half2 ha = *reinterpret_cast<__half2*>(&A);
        __half2 hb = *reinterpret_cast<__half2*>(&B);
        float na0 = fmaf(__low2float(ha),  sa0, ha0);
        float na1 = fmaf(__high2float(ha), sa1, ha1);
        float nb0 = fmaf(__low2float(hb),  sb0, hb0);
        float nb1 = fmaf(__high2float(hb), sb1, hb1);
        a0 += fsig(na0) * fsp(nb0);
        a1 += fsig(na1) * fsp(nb1);
    }
    float2* hp = (float2*)(g_h + (size_t)gw * HDIM) + lane;
    float2 hv = *hp;
    hv.x += a0; hv.y += a1;
    *hp = hv;
    __half2 hh = __floats2half2_rn(hv.x, hv.y);
    g_hh[(size_t)gw * 32 + lane] = *reinterpret_cast<uint32_t*>(&hh);
    if (doPool) {
        int g = gidArr[gw];
        float* pr = g_pool + (size_t)g * HDIM + 2 * lane;
        asm volatile("red.global.add.v2.f32 [%0], {%1, %2};"
                     :: "l"(pr), "f"(hv.x), "f"(hv.y) : "memory");
        if (lane == 0) atomicAdd(&g_cnt[g], 1.0f);
    }
}

// ------------------------- 5. prediction head (self-zeroing pool) -----------
__global__ void __launch_bounds__(PRED_H)
head_kernel(const float* __restrict__ fcW, const float* __restrict__ fcb,
            const float* __restrict__ outW, const float* __restrict__ outb,
            float* __restrict__ out) {
    __shared__ float sp[HDIM];
    __shared__ float red[PRED_H];
    int g = blockIdx.x, t = threadIdx.x;
    if (t < HDIM) {
        float c = g_cnt[g];
        sp[t] = g_pool[(size_t)g * HDIM + t] / fmaxf(c, 1.0f);
    }
    __syncthreads();
    float acc = fcb[t];
    #pragma unroll
    for (int k = 0; k < HDIM; k++) acc = fmaf(sp[k], fcW[k * PRED_H + t], acc);
    red[t] = fmaxf(acc, 0.f) + log1pf(expf(-fabsf(acc)));
    red[t] *= outW[t];
    __syncthreads();
    for (int sft = PRED_H / 2; sft > 0; sft >>= 1) {
        if (t < sft) red[t] += red[t + sft];
        __syncthreads();
    }
    if (t == 0) out[g] = red[0] + outb[0];
    __syncthreads();
    if (t < HDIM) g_pool[(size_t)g * HDIM + t] = 0.f;
    if (t == HDIM) g_cnt[g] = 0.f;
}

// ------------------------- launch -------------------------------------------
extern "C" void kernel_launch(void* const* d_in, const int* in_sizes, int n_in,
                              void* d_out, int out_size) {
    const float* node_feats = (const float*)d_in[0];
    const int*   edge_index = (const int*)d_in[1];
    const float* edge_feats = (const float*)d_in[2];
    const int*   graph_id   = (const int*)d_in[3];
    const float* emb_W      = (const float*)d_in[4];
    const float* emb_b      = (const float*)d_in[5];
    const float* conv_W     = (const float*)d_in[6];
    // d_in[7] = conv_b: zeros; constant bias cancels exactly in BN.
    const float* bn_gamma   = (const float*)d_in[8];
    const float* bn_beta    = (const float*)d_in[9];
    const float* fc_W       = (const float*)d_in[10];
    const float* fc_b       = (const float*)d_in[11];
    const float* out_W      = (const float*)d_in[12];
    const float* out_b      = (const float*)d_in[13];

    int nNodes  = in_sizes[0] / NODE_DIM;
    int nEdges  = in_sizes[1] / 2;
    int nConv   = in_sizes[6] / (KD * OUTC);

    int nsm = 148;
    cudaDeviceGetAttribute(&nsm, cudaDevAttrMultiProcessorCount, 0);

    size_t convSmem = (size_t)SMEM_WORDS * 4;   // 92160 B
    cudaFuncSetAttribute(conv_mma_kernel,
                         cudaFuncAttributeMaxDynamicSharedMemorySize, (int)convSmem);

    emb_kernel<<<2048, 256>>>(node_feats, emb_W, emb_b, nNodes);
    hsplit_kernel<<<(nNodes * 32 + 255) / 256, 256>>>(nNodes);
    {
        long long tot = (long long)nEdges * 24;
        efsplit_kernel<<<(int)((tot + 255) / 256), 256>>>(edge_feats, nEdges);
    }

    // ---- CSR build (edge_index constant across layers) ----
    int eb = (nEdges + 255) / 256;
    int nb1 = (nNodes + 1023) / 1024;
    zero_cnt_kernel<<<(nNodes + 255) / 256, 256>>>(nNodes);
    hist_kernel<<<eb, 256>>>(edge_index, nEdges);
    scan1_kernel<<<nb1, 1024>>>(nNodes);
    scan2_kernel<<<1, 1024>>>(nb1);
    scan3_kernel<<<nb1, 1024>>>(nNodes, nEdges);
    scatter_kernel<<<eb, 256>>>(edge_index, nEdges);

    int nTiles = (nEdges + 127) / 128;
    float invE = 1.0f / (float)nEdges;
    int gateBlocks = (nNodes + 7) / 8;
    for (int l = 0; l < nConv; l++) {
        bfrag_kernel<<<(BU2 + 255) / 256, 256>>>(conv_W + (size_t)l * KD * OUTC);
        conv_mma_kernel<<<2 * nsm, 256, convSmem>>>(edge_index, nEdges, nTiles);
        bn_coef_kernel<<<1, OUTC>>>(bn_gamma + l * OUTC, bn_beta + l * OUTC, invE);
        csr_gate_kernel<<<gateBlocks, 256>>>(graph_id, nNodes, l == nConv - 1);
    }

    head_kernel<<<out_size, PRED_H>>>(fc_W, fc_b, out_W, out_b, (float*)d_out);
}